// round 14
// baseline (speedup 1.0000x reference)
#include <cuda_runtime.h>
#include <cuda_fp16.h>
#include <math.h>
#include <stdint.h>

// Problem constants
#define NN 8192
#define EE 32768
#define EP 40960      // EE + NN self loops
#define DD 768
#define H1H 8
#define CC 768
#define F1 6144       // H1H * CC
#define MM 2048
#define NEG_SLOPE 0.2f

// fp16 GEMM (128x128 tile, 256 threads, 4-stage, 2 CTAs/SM)
#define BM 128
#define BN 128
#define BK 32
#define GT 256
#define STG 4
#define HPAD 40
#define HTILE (128 * HPAD)

// ---------------- scratch (device globals) ----------------
__device__ __half g_H1h[(size_t)NN * F1];
__device__ __half g_out1h[(size_t)NN * F1];
__device__ float  g_H2p[(size_t)2 * NN * CC];   // split-K partials; [0] becomes H2
__device__ float  g_out2[(size_t)NN * CC];
__device__ __half g_xh[(size_t)NN * DD];
__device__ float g_att1[2 * NN * H1H];          // [asrc | adst], one memset
__device__ float g_asrc2[NN], g_adst2[NN];
__device__ int g_src[EP], g_dst[EP], g_midx[MM];
__device__ __half g_cath[(size_t)MM * 2 * CC];
__device__ float g_fc[(size_t)MM * CC];
__device__ __half g_W1T[(size_t)F1 * DD];
__device__ __half g_W2T[(size_t)CC * F1];
__device__ __half g_fcwTh[(size_t)CC * 2 * CC];
// CSR
__device__ int g_cnt[NN];
__device__ int g_rptr[NN + 1];
__device__ int g_woff[NN];
__device__ int g_csrc[EP];

// ---------------- helpers ----------------
__device__ __forceinline__ int load_idx(const void* p, long long i, int is64) {
    if (is64) return (int)((const long long*)p)[i];
    return ((const int*)p)[i];
}
__device__ __forceinline__ uint32_t smem_u32(const void* p) {
    uint32_t a;
    asm("{ .reg .u64 t; cvta.to.shared.u64 t, %1; cvt.u32.u64 %0, t; }"
        : "=r"(a) : "l"(p));
    return a;
}

#define LDSM4(r0, r1, r2, r3, addr) \
    asm volatile("ldmatrix.sync.aligned.m8n8.x4.shared.b16 {%0,%1,%2,%3}, [%4];" \
                 : "=r"(r0), "=r"(r1), "=r"(r2), "=r"(r3) : "r"(addr))

// ---------------- prep: dtype detect + index decode + degree count ---------
__global__ void k_prep(const void* ebuf, const void* mbuf) {
    const unsigned* eu = (const unsigned*)ebuf;
    const unsigned* mu = (const unsigned*)mbuf;
    int fe = 1, fm = 1;
#pragma unroll
    for (int i = 0; i < 16; i++) if (eu[2 * i + 1] != 0u) { fe = 0; break; }
#pragma unroll
    for (int i = 0; i < 16; i++) if (mu[2 * i + 1] != 0u) { fm = 0; break; }

    int i = blockIdx.x * blockDim.x + threadIdx.x;
    if (i < EP) {
        int s, d;
        if (i < EE) {
            s = load_idx(ebuf, i, fe);
            d = load_idx(ebuf, (long long)EE + i, fe);
        } else {
            s = i - EE;
            d = i - EE;
        }
        g_src[i] = s;
        g_dst[i] = d;
        atomicAdd(&g_cnt[d], 1);
    }
    if (i < MM) g_midx[i] = load_idx(mbuf, i, fm);
}

// ---------------- CSR build ----------------
__global__ void k_scan() {
    __shared__ int wsum[32];
    int tid = threadIdx.x;
    int lane = tid & 31, w = tid >> 5;
    int base = tid * 8;
    int loc[8];
    int s = 0;
#pragma unroll
    for (int i = 0; i < 8; i++) { loc[i] = s; s += g_cnt[base + i]; }
    int inc = s;
#pragma unroll
    for (int o = 1; o < 32; o <<= 1) {
        int v = __shfl_up_sync(~0u, inc, o);
        if (lane >= o) inc += v;
    }
    if (lane == 31) wsum[w] = inc;
    __syncthreads();
    if (w == 0) {
        int v = wsum[lane];
#pragma unroll
        for (int o = 1; o < 32; o <<= 1) {
            int t = __shfl_up_sync(~0u, v, o);
            if (lane >= o) v += t;
        }
        wsum[lane] = v;
    }
    __syncthreads();
    int off = inc - s + (w ? wsum[w - 1] : 0);
#pragma unroll
    for (int i = 0; i < 8; i++) {
        g_rptr[base + i] = off + loc[i];
        g_woff[base + i] = off + loc[i];
    }
    if (tid == 1023) g_rptr[NN] = EP;
}
__global__ void k_fill() {
    int i = blockIdx.x * blockDim.x + threadIdx.x;
    if (i >= EP) return;
    int pos = atomicAdd(&g_woff[g_dst[i]], 1);
    g_csrc[pos] = g_src[i];
}

// ---------------- fused pre-pass: cvt(x) + W1T + W2T + fcwT ----------------
#define NB_CVT 6144
#define NB_W1  (192 * 24)
#define NB_W2  (24 * 192)
#define NB_FC  (24 * 48)
__device__ __forceinline__ void tr_tile(const float* __restrict__ in,
                                        __half* __restrict__ out,
                                        int R, int C, int bx, int by, int tid) {
    __shared__ float t[32][33];
    int tx = tid & 31, ty = tid >> 5;
    int x = bx * 32 + tx;
#pragma unroll
    for (int j = 0; j < 32; j += 8) {
        int y = by * 32 + ty + j;
        t[ty + j][tx] = in[(size_t)y * C + x];
    }
    __syncthreads();
    int ox = by * 32 + tx;
#pragma unroll
    for (int j = 0; j < 32; j += 8) {
        int oy = bx * 32 + ty + j;
        out[(size_t)oy * R + ox] = __float2half(t[tx][ty + j]);
    }
}
__global__ __launch_bounds__(256)
void k_preall(const float4* __restrict__ x4, __half2* __restrict__ xh2,
              const float* __restrict__ W1, __half* __restrict__ W1T,
              const float* __restrict__ W2, __half* __restrict__ W2T,
              const float* __restrict__ fcw, __half* __restrict__ fcwT) {
    int b = blockIdx.x, tid = threadIdx.x;
    if (b < NB_CVT) {
        size_t i = (size_t)b * 256 + tid;
        float4 v = x4[i];
        xh2[2 * i + 0] = __floats2half2_rn(v.x, v.y);
        xh2[2 * i + 1] = __floats2half2_rn(v.z, v.w);
        return;
    }
    b -= NB_CVT;
    if (b < NB_W1) { tr_tile(W1, W1T, DD, F1, b % 192, b / 192, tid); return; }
    b -= NB_W1;
    if (b < NB_W2) { tr_tile(W2, W2T, F1, CC, b % 24, b / 24, tid); return; }
    b -= NB_W2;
    tr_tile(fcw, fcwT, 2 * CC, CC, b % 24, b / 24, tid);
}

// ---------------- fp16 mma.sync GEMM (4-stage pipeline) --------------------
__device__ __forceinline__ void mma16816(float* c, const uint32_t* a,
                                         const uint32_t* b) {
    asm volatile(
        "mma.sync.aligned.m16n8k16.row.col.f32.f16.f16.f32 "
        "{%0,%1,%2,%3}, {%4,%5,%6,%7}, {%8,%9}, {%0,%1,%2,%3};"
        : "+f"(c[0]), "+f"(c[1]), "+f"(c[2]), "+f"(c[3])
        : "r"(a[0]), "r"(a[1]), "r"(a[2]), "r"(a[3]), "r"(b[0]), "r"(b[1]));
}
template <typename OutT, bool DOATT>
__global__ __launch_bounds__(GT, 2)
void hgemm(const __half* __restrict__ A, const __half* __restrict__ Bt,
           OutT* __restrict__ C, int Nd, int Kiter, int ldK, size_t partStride,
           const float* __restrict__ attA, const float* __restrict__ attD,
           float* __restrict__ outA, float* __restrict__ outD, int heads) {
    extern __shared__ __half hsm[];
    int tid = threadIdx.x;
    int wid = tid >> 5, lane = tid & 31;
    int wr = wid & 1, wc = wid >> 1;
    int g = lane >> 2, q = lane & 3;
    int row0 = blockIdx.y * BM, col0 = blockIdx.x * BN;
    int koff = blockIdx.z * Kiter;
    C += (size_t)blockIdx.z * partStride;
    const int NIT = Kiter / BK;
    uint32_t sbase = smem_u32(hsm);

    uint32_t a_off = (uint32_t)(((wr * 64 + (lane & 15)) * HPAD
                                 + ((lane & 16) ? 8 : 0)) * 2);
    uint32_t b_off = (uint32_t)(((wc * 32 + (lane & 7) + ((lane & 16) ? 8 : 0)) * HPAD
                                 + ((lane & 8) ? 8 : 0)) * 2);

    auto issue = [&](int s, int kt) {
        uint32_t as = sbase + (uint32_t)(s * 2 * HTILE) * 2u;
        uint32_t bs = as + (uint32_t)HTILE * 2u;
#pragma unroll
        for (int l = 0; l < 2; l++) {
            int p = tid + l * GT;
            int r = p >> 2, c0 = (p & 3) << 3;
            const __half* ga = A + (size_t)(row0 + r) * ldK + koff + kt + c0;
            uint32_t da = as + (uint32_t)(r * HPAD + c0) * 2u;
            asm volatile("cp.async.cg.shared.global [%0], [%1], 16;"
                         :: "r"(da), "l"(ga) : "memory");
            const __half* gb = Bt + (size_t)(col0 + r) * ldK + koff + kt + c0;
            uint32_t db = bs + (uint32_t)(r * HPAD + c0) * 2u;
            asm volatile("cp.async.cg.shared.global [%0], [%1], 16;"
                         :: "r"(db), "l"(gb) : "memory");
        }
        asm volatile("cp.async.commit_group;" ::: "memory");
    };

    float acc[4][4][4];
#pragma unroll
    for (int a = 0; a < 4; a++)
#pragma unroll
        for (int b = 0; b < 4; b++)
#pragma unroll
            for (int c = 0; c < 4; c++) acc[a][b][c] = 0.f;

    issue(0, 0);
    issue(1, BK);
    issue(2, 2 * BK);

    for (int i = 0; i < NIT; i++) {
        if (i + 3 < NIT) {
            issue((i + 3) % STG, (i + 3) * BK);
            asm volatile("cp.async.wait_group 3;" ::: "memory");
        } else {
            asm volatile("cp.async.wait_group 0;" ::: "memory");
        }
        __syncthreads();

        uint32_t as = sbase + (uint32_t)((i % STG) * 2 * HTILE) * 2u;
        uint32_t bs = as + (uint32_t)HTILE * 2u;
#pragma unroll
        for (int ki = 0; ki < 2; ki++) {
            uint32_t kb2 = (uint32_t)(ki * 16 * 2);
            uint32_t af[4][4], bf[4][2];
#pragma unroll
            for (int mi = 0; mi < 4; mi++) {
                uint32_t addr = as + a_off + (uint32_t)(mi * 16 * HPAD * 2) + kb2;
                LDSM4(af[mi][0], af[mi][1], af[mi][2], af[mi][3], addr);
            }
#pragma unroll
            for (int np = 0; np < 2; np++) {
                uint32_t addr = bs + b_off + (uint32_t)(np * 16 * HPAD * 2) + kb2;
                LDSM4(bf[2 * np][0], bf[2 * np][1],
                      bf[2 * np + 1][0], bf[2 * np + 1][1], addr);
            }
#pragma unroll
            for (int mi = 0; mi < 4; mi++)
#pragma unroll
                for (int ni = 0; ni < 4; ni++)
                    mma16816(acc[mi][ni], af[mi], bf[ni]);
        }
        __syncthreads();
    }

#pragma unroll
    for (int mi = 0; mi < 4; mi++) {
        int r0 = row0 + wr * 64 + mi * 16 + g;
#pragma unroll
        for (int ni = 0; ni < 4; ni++) {
            int col = col0 + wc * 32 + ni * 8 + q * 2;
            OutT* p0 = C + (size_t)r0 * Nd + col;
            OutT* p1 = p0 + (size_t)8 * Nd;
            if (sizeof(OutT) == 2) {
                *(__half2*)p0 = __floats2half2_rn(acc[mi][ni][0], acc[mi][ni][1]);
                *(__half2*)p1 = __floats2half2_rn(acc[mi][ni][2], acc[mi][ni][3]);
            } else {
                p0[0] = (OutT)acc[mi][ni][0]; p0[1] = (OutT)acc[mi][ni][1];
                p1[0] = (OutT)acc[mi][ni][2]; p1[1] = (OutT)acc[mi][ni][3];
            }
        }
    }

    if (DOATT) {
        int head = col0 / CC;
        float a0[4], a1[4], d0[4], d1[4];
#pragma unroll
        for (int ni = 0; ni < 4; ni++) {
            int lc = col0 + wc * 32 + ni * 8 + q * 2;
            a0[ni] = attA[lc]; a1[ni] = attA[lc + 1];
            d0[ni] = attD[lc]; d1[ni] = attD[lc + 1];
        }
#pragma unroll
        for (int mi = 0; mi < 4; mi++) {
            float sa0 = 0.f, sd0 = 0.f, sa1 = 0.f, sd1 = 0.f;
#pragma unroll
            for (int ni = 0; ni < 4; ni++) {
                sa0 += acc[mi][ni][0] * a0[ni] + acc[mi][ni][1] * a1[ni];
                sd0 += acc[mi][ni][0] * d0[ni] + acc[mi][ni][1] * d1[ni];
                sa1 += acc[mi][ni][2] * a0[ni] + acc[mi][ni][3] * a1[ni];
                sd1 += acc[mi][ni][2] * d0[ni] + acc[mi][ni][3] * d1[ni];
            }
#pragma unroll
            for (int o = 1; o < 4; o <<= 1) {
                sa0 += __shfl_xor_sync(~0u, sa0, o);
                sd0 += __shfl_xor_sync(~0u, sd0, o);
                sa1 += __shfl_xor_sync(~0u, sa1, o);
                sd1 += __shfl_xor_sync(~0u, sd1, o);
            }
            if (q == 0) {
                int r0 = row0 + wr * 64 + mi * 16 + g;
                atomicAdd(&outA[r0 * heads + head], sa0);
                atomicAdd(&outD[r0 * heads + head], sd0);
                atomicAdd(&outA[(r0 + 8) * heads + head], sa1);
                atomicAdd(&outD[(r0 + 8) * heads + head], sd1);
            }
        }
    }
}

// ---------------- split-K reduce + layer-2 attention dots ------------------
__global__ __launch_bounds__(256)
void k_red2att(const float* __restrict__ p0, const float* __restrict__ p1,
               const float* __restrict__ as2, const float* __restrict__ ad2,
               float* __restrict__ H2, float* __restrict__ asum,
               float* __restrict__ dsum) {
    int n = blockIdx.x, tid = threadIdx.x;
    int lane = tid & 31, w = tid >> 5;
    const float* a = p0 + (size_t)n * CC;
    const float* b = p1 + (size_t)n * CC;
    float s1 = 0.f, s2 = 0.f;
#pragma unroll
    for (int k = 0; k < 3; k++) {
        int c = tid + k * 256;
        float v = a[c] + b[c];
        H2[(size_t)n * CC + c] = v;
        s1 += v * as2[c];
        s2 += v * ad2[c];
    }
#pragma unroll
    for (int o = 16; o; o >>= 1) {
        s1 += __shfl_xor_sync(~0u, s1, o);
        s2 += __shfl_xor_sync(~0u, s2, o);
    }
    __shared__ float r1[8], r2[8];
    if (lane == 0) { r1[w] = s1; r2[w] = s2; }
    __syncthreads();
    if (tid == 0) {
        float t1 = 0.f, t2 = 0.f;
#pragma unroll
        for (int i = 0; i < 8; i++) { t1 += r1[i]; t2 += r2[i]; }
        asum[n] = t1;
        dsum[n] = t2;
    }
}

// ---------------- fused layer-1 aggregation (fp16, uint4 loads) ------------
#define CH1 64
__global__ __launch_bounds__(256)
void k_agg1(const uint4* __restrict__ H4, const float* __restrict__ asrc,
            const float* __restrict__ adst, const float* __restrict__ bias,
            uint4* __restrict__ out) {
    int d = blockIdx.x;
    int tid = threadIdx.x, wid = tid >> 5, lane = tid & 31;
    int beg = g_rptr[d], end = g_rptr[d + 1];
    __shared__ float s_m[H1H], s_den[H1H];
    __shared__ float s_coef[CH1 * H1H];
    __shared__ int s_src[CH1];

    {
        int h = wid;
        float adh = adst[d * H1H + h];
        float mx = -1e30f;
        for (int i = beg + lane; i < end; i += 32) {
            float v = asrc[g_csrc[i] * H1H + h] + adh;
            v = (v > 0.f) ? v : NEG_SLOPE * v;
            mx = fmaxf(mx, v);
        }
#pragma unroll
        for (int o = 16; o; o >>= 1) mx = fmaxf(mx, __shfl_xor_sync(~0u, mx, o));
        float sum = 0.f;
        for (int i = beg + lane; i < end; i += 32) {
            float v = asrc[g_csrc[i] * H1H + h] + adh;
            v = (v > 0.f) ? v : NEG_SLOPE * v;
            sum += expf(v - mx);
        }
#pragma unroll
        for (int o = 16; o; o >>= 1) sum += __shfl_xor_sync(~0u, sum, o);
        if (lane == 0) { s_m[h] = mx; s_den[h] = sum + 1e-16f; }
    }
    __syncthreads();

    int hk[3][4];
#pragma unroll
    for (int k = 0; k < 3; k++)
#pragma unroll
        for (int j = 0; j < 4; j++)
            hk[k][j] = (4 * (tid + k * 256) + j) / 384;
    float2 acc[3][4];
#pragma unroll
    for (int k = 0; k < 3; k++)
#pragma unroll
        for (int j = 0; j < 4; j++) acc[k][j] = make_float2(0.f, 0.f);

    for (int cb = beg; cb < end; cb += CH1) {
        int ch = min(CH1, end - cb);
        for (int i = tid; i < ch * H1H; i += 256) {
            int e = i >> 3, h = i & 7;
            int s = g_csrc[cb + e];
            float v = asrc[s * H1H + h] + adst[d * H1H + h];
            v = (v > 0.f) ? v : NEG_SLOPE * v;
            s_coef[i] = expf(v - s_m[h]) / s_den[h];
            if (h == 0) s_src[e] = s;
        }
        __syncthreads();
        for (int e = 0; e < ch; e++) {
            const uint4* hp = H4 + (size_t)s_src[e] * (F1 / 8);
            const float* cf = &s_coef[e * H1H];
#pragma unroll
            for (int k = 0; k < 3; k++) {
                uint4 u = hp[tid + k * 256];
                const __half2* hv = (const __half2*)&u;
#pragma unroll
                for (int j = 0; j < 4; j++) {
                    float2 v = __half22float2(hv[j]);
                    float c = cf[hk[k][j]];
                    acc[k][j].x += c * v.x;
                    acc[k][j].y += c * v.y;
                }
            }
        }
        __syncthreads();
    }
#pragma unroll
    for (int k = 0; k < 3; k++) {
        uint4 o;
        __half2* ov = (__half2*)&o;
#pragma unroll
        for (int j = 0; j < 4; j++) {
            int c = 2 * (4 * (tid + k * 256) + j);
            float v0 = acc[k][j].x + bias[c];
            float v1 = acc[k][j].y + bias[c + 1];
            v0 = (v0 > 0.f) ? v0 : expm1f(v0);
            v1 = (v1 > 0.f) ? v1 : expm1f(v1);
            ov[j] = __floats2half2_rn(v0, v1);
        }
        out[(size_t)d * (F1 / 8) + tid + k * 256] = o;
    }
}

// ---------------- fused layer-2 aggregation (fp32) ----------------
#define CH2 128
__global__ __launch_bounds__(256)
void k_agg2(const float* __restrict__ H, const float* __restrict__ asrc,
            const float* __restrict__ adst, float* __restrict__ out) {
    int d = blockIdx.x;
    int tid = threadIdx.x, wid = tid >> 5, lane = tid & 31;
    int beg = g_rptr[d], end = g_rptr[d + 1];
    __shared__ float s_m, s_den;
    __shared__ float s_coef[CH2];
    __shared__ int s_src[CH2];

    if (wid == 0) {
        float adh = adst[d];
        float mx = -1e30f;
        for (int i = beg + lane; i < end; i += 32) {
            float v = asrc[g_csrc[i]] + adh;
            v = (v > 0.f) ? v : NEG_SLOPE * v;
            mx = fmaxf(mx, v);
        }
#pragma unroll
        for (int o = 16; o; o >>= 1) mx = fmaxf(mx, __shfl_xor_sync(~0u, mx, o));
        float sum = 0.f;
        for (int i = beg + lane; i < end; i += 32) {
            float v = asrc[g_csrc[i]] + adh;
            v = (v > 0.f) ? v : NEG_SLOPE * v;
            sum += expf(v - mx);
        }
#pragma unroll
        for (int o = 16; o; o >>= 1) sum += __shfl_xor_sync(~0u, sum, o);
        if (lane == 0) { s_m = mx; s_den = sum + 1e-16f; }
    }
    __syncthreads();

    float acc[3] = {0.f, 0.f, 0.f};
    for (int cb = beg; cb < end; cb += CH2) {
        int ch = min(CH2, end - cb);
        for (int i = tid; i < ch; i += 256) {
            int s = g_csrc[cb + i];
            float v = asrc[s] + adst[d];
            v = (v > 0.f) ? v : NEG_SLOPE * v;
            s_coef[i] = expf(v - s_m) / s_den;
            s_src[i] = s;
        }
        __syncthreads();
        for (int e = 0; e < ch; e++) {
            const float* hp = H + (size_t)s_src[e] * CC;
            float cf = s_coef[e];
#pragma unroll
            for (int k = 0; k < 3; k++)
                acc[k] += cf * hp[tid + k * 256];
        }
        __syncthreads();
    }
#pragma unroll
    for (int k = 0; k < 3; k++)
        out[(size_t)d * CC + tid + k * 256] = acc[k];
}

// ---------------- gather + concat -> fp16 (adds b2) ----------------
__global__ void k_cath(const float* __restrict__ out2, const float* __restrict__ b2,
                       const float* __restrict__ x, __half* __restrict__ cat) {
    int i = blockIdx.x * blockDim.x + threadIdx.x;
    if (i >= MM * CC) return;
    int m = i / CC, c = i - m * CC;
    int idx = g_midx[m];
    cat[(size_t)m * (2 * CC) + c] = __float2half(out2[(size_t)idx * CC + c] + b2[c]);
    cat[(size_t)m * (2 * CC) + CC + c] = __float2half(x[(size_t)idx * DD + c]);
}

// ---------------- classifier (warp per row, adds fcb) ----------------
__global__ void k_cls(const float* __restrict__ fc, const float* __restrict__ fcb,
                      const float* __restrict__ w, const float* __restrict__ b,
                      float* __restrict__ out) {
    int gw = (blockIdx.x * blockDim.x + threadIdx.x) >> 5;
    int lane = threadIdx.x & 31;
    if (gw >= MM) return;
    const float* fp = fc + (size_t)gw * CC;
    float s0 = 0.f, s1 = 0.f;
    for (int c = lane; c < CC; c += 32) {
        float v = fp[c] + fcb[c];
        s0 += v * w[c * 2 + 0];
        s1 += v * w[c * 2 + 1];
    }
#pragma unroll
    for (int o = 16; o; o >>= 1) {
        s0 += __shfl_xor_sync(0xffffffffu, s0, o);
        s1 += __shfl_xor_sync(0xffffffffu, s1, o);
    }
    if (lane == 0) {
        out[gw * 2 + 0] = s0 + b[0];
        out[gw * 2 + 1] = s1 + b[1];
    }
}

// ---------------- launch ----------------
extern "C" void kernel_launch(void* const* d_in, const int* in_sizes, int n_in,
                              void* d_out, int out_size) {
    (void)in_sizes; (void)n_in; (void)out_size;
    const float* x   = (const float*)d_in[0];
    const void*  eix = d_in[1];
    const void*  mix = d_in[2];
    const float* W1  = (const float*)d_in[3];
    const float* as1 = (const float*)d_in[4];
    const float* ad1 = (const float*)d_in[5];
    const float* b1  = (const float*)d_in[6];
    const float* W2  = (const float*)d_in[7];
    const float* as2 = (const float*)d_in[8];
    const float* ad2 = (const float*)d_in[9];
    const float* b2  = (const float*)d_in[10];
    const float* fcw = (const float*)d_in[11];
    const float* fcb = (const float*)d_in[12];
    const float* clw = (const float*)d_in[13];
    const float* clb = (const float*)d_in[14];
    float* out = (float*)d_out;

    void *pH1h, *pOut1h, *pH2p, *pOut2, *pXh, *pAtt1, *pAs2, *pAd2;
    void *pCath, *pFc, *pW1T, *pW2T, *pFcwTh, *pCnt;
    cudaGetSymbolAddress(&pH1h, g_H1h);
    cudaGetSymbolAddress(&pOut1h, g_out1h);
    cudaGetSymbolAddress(&pH2p, g_H2p);
    cudaGetSymbolAddress(&pOut2, g_out2);
    cudaGetSymbolAddress(&pXh, g_xh);
    cudaGetSymbolAddress(&pAtt1, g_att1);
    cudaGetSymbolAddress(&pAs2, g_asrc2);
    cudaGetSymbolAddress(&pAd2, g_adst2);
    cudaGetSymbolAddress(&pCath, g_cath);
    cudaGetSymbolAddress(&pFc, g_fc);
    cudaGetSymbolAddress(&pW1T, g_W1T);
    cudaGetSymbolAddress(&pW2T, g_W2T);
    cudaGetSymbolAddress(&pFcwTh, g_fcwTh);
    cudaGetSymbolAddress(&pCnt, g_cnt);

    float* As1 = (float*)pAtt1;
    float* Ad1 = (float*)pAtt1 + (size_t)NN * H1H;
    float* H2  = (float*)pH2p;
    float* H2b = (float*)pH2p + (size_t)NN * CC;

    const int H_SMEM = STG * 2 * HTILE * 2;   // 81920 B (4-stage)
    cudaFuncSetAttribute(hgemm<__half, true>,
                         cudaFuncAttributeMaxDynamicSharedMemorySize, H_SMEM);
    cudaFuncSetAttribute(hgemm<float, false>,
                         cudaFuncAttributeMaxDynamicSharedMemorySize, H_SMEM);

    cudaMemsetAsync(pCnt, 0, NN * sizeof(int));
    cudaMemsetAsync(pAtt1, 0, (size_t)2 * NN * H1H * sizeof(float));
    k_prep<<<(EP + 255) / 256, 256>>>(eix, mix);
    k_scan<<<1, 1024>>>();
    k_fill<<<(EP + 255) / 256, 256>>>();

    k_preall<<<NB_CVT + NB_W1 + NB_W2 + NB_FC, 256>>>(
        (const float4*)x, (__half2*)pXh,
        W1, (__half*)pW1T, W2, (__half*)pW2T, fcw, (__half*)pFcwTh);

    // ---- layer 1 (att dots fused into epilogue) ----
    hgemm<__half, true><<<dim3(F1 / BN, NN / BM, 1), GT, H_SMEM>>>(
        (const __half*)pXh, (const __half*)pW1T, (__half*)pH1h,
        F1, DD, DD, 0, as1, ad1, As1, Ad1, H1H);
    k_agg1<<<NN, 256>>>((const uint4*)pH1h, As1, Ad1, b1, (uint4*)pOut1h);

    // ---- layer 2 (split-K=2; reduce fuses att dots) ----
    hgemm<float, false><<<dim3(CC / BN, NN / BM, 2), GT, H_SMEM>>>(
        (const __half*)pOut1h, (const __half*)pW2T, H2,
        CC, F1 / 2, F1, (size_t)NN * CC, nullptr, nullptr, nullptr, nullptr, 1);
    k_red2att<<<NN, 256>>>(H2, H2b, as2, ad2, H2, (float*)pAs2, (float*)pAd2);
    k_agg2<<<NN, 256>>>(H2, (const float*)pAs2, (const float*)pAd2, (float*)pOut2);

    // ---- head ----
    k_cath<<<(MM * CC + 255) / 256, 256>>>((const float*)pOut2, b2, x,
                                           (__half*)pCath);
    hgemm<float, false><<<dim3(CC / BN, MM / BM, 1), GT, H_SMEM>>>(
        (const __half*)pCath, (const __half*)pFcwTh, (float*)pFc,
        CC, 2 * CC, 2 * CC, 0, nullptr, nullptr, nullptr, nullptr, 1);
    k_cls<<<(MM * 32 + 255) / 256, 256>>>((const float*)pFc, fcb, clw, clb, out);
}

// round 15
// speedup vs baseline: 1.5480x; 1.5480x over previous
#include <cuda_runtime.h>
#include <cuda_fp16.h>
#include <math.h>
#include <stdint.h>

// Problem constants
#define NN 8192
#define EE 32768
#define EP 40960      // EE + NN self loops
#define DD 768
#define H1H 8
#define CC 768
#define F1 6144       // H1H * CC
#define MM 2048
#define NEG_SLOPE 0.2f

// fp16 GEMM (128x128 tile, 256 threads, 3-stage, 2 CTAs/SM) -- FROZEN CONFIG
#define BM 128
#define BN 128
#define BK 32
#define GT 256
#define STG 3
#define HPAD 40
#define HTILE (128 * HPAD)

// ---------------- scratch (device globals) ----------------
__device__ __half g_H1h[(size_t)NN * F1];
__device__ __half g_out1h[(size_t)NN * F1];
__device__ float  g_H2p[(size_t)2 * NN * CC];   // split-K partials; [0] becomes H2
__device__ float  g_out2[(size_t)NN * CC];
__device__ __half g_xh[(size_t)NN * DD];
__device__ float g_att1[2 * NN * H1H];          // [asrc | adst], one memset
__device__ float g_asrc2[NN], g_adst2[NN];
__device__ int g_src[EP], g_dst[EP], g_midx[MM];
__device__ __half g_cath[(size_t)MM * 2 * CC];
__device__ float g_fc[(size_t)MM * CC];
__device__ __half g_W1T[(size_t)F1 * DD];
__device__ __half g_W2T[(size_t)CC * F1];
__device__ __half g_fcwTh[(size_t)CC * 2 * CC];
// CSR
__device__ int g_cnt[NN];
__device__ int g_rptr[NN + 1];
__device__ int g_woff[NN];
__device__ int g_csrc[EP];

// ---------------- helpers ----------------
__device__ __forceinline__ int load_idx(const void* p, long long i, int is64) {
    if (is64) return (int)((const long long*)p)[i];
    return ((const int*)p)[i];
}
__device__ __forceinline__ uint32_t smem_u32(const void* p) {
    uint32_t a;
    asm("{ .reg .u64 t; cvta.to.shared.u64 t, %1; cvt.u32.u64 %0, t; }"
        : "=r"(a) : "l"(p));
    return a;
}

#define LDSM4(r0, r1, r2, r3, addr) \
    asm volatile("ldmatrix.sync.aligned.m8n8.x4.shared.b16 {%0,%1,%2,%3}, [%4];" \
                 : "=r"(r0), "=r"(r1), "=r"(r2), "=r"(r3) : "r"(addr))

// ---------------- prep: dtype detect + index decode + degree count ---------
__global__ void k_prep(const void* ebuf, const void* mbuf) {
    const unsigned* eu = (const unsigned*)ebuf;
    const unsigned* mu = (const unsigned*)mbuf;
    int fe = 1, fm = 1;
#pragma unroll
    for (int i = 0; i < 16; i++) if (eu[2 * i + 1] != 0u) { fe = 0; break; }
#pragma unroll
    for (int i = 0; i < 16; i++) if (mu[2 * i + 1] != 0u) { fm = 0; break; }

    int i = blockIdx.x * blockDim.x + threadIdx.x;
    if (i < EP) {
        int s, d;
        if (i < EE) {
            s = load_idx(ebuf, i, fe);
            d = load_idx(ebuf, (long long)EE + i, fe);
        } else {
            s = i - EE;
            d = i - EE;
        }
        g_src[i] = s;
        g_dst[i] = d;
        atomicAdd(&g_cnt[d], 1);
    }
    if (i < MM) g_midx[i] = load_idx(mbuf, i, fm);
}

// ---------------- CSR build ----------------
__global__ void k_scan() {
    __shared__ int wsum[32];
    int tid = threadIdx.x;
    int lane = tid & 31, w = tid >> 5;
    int base = tid * 8;
    int loc[8];
    int s = 0;
#pragma unroll
    for (int i = 0; i < 8; i++) { loc[i] = s; s += g_cnt[base + i]; }
    int inc = s;
#pragma unroll
    for (int o = 1; o < 32; o <<= 1) {
        int v = __shfl_up_sync(~0u, inc, o);
        if (lane >= o) inc += v;
    }
    if (lane == 31) wsum[w] = inc;
    __syncthreads();
    if (w == 0) {
        int v = wsum[lane];
#pragma unroll
        for (int o = 1; o < 32; o <<= 1) {
            int t = __shfl_up_sync(~0u, v, o);
            if (lane >= o) v += t;
        }
        wsum[lane] = v;
    }
    __syncthreads();
    int off = inc - s + (w ? wsum[w - 1] : 0);
#pragma unroll
    for (int i = 0; i < 8; i++) {
        g_rptr[base + i] = off + loc[i];
        g_woff[base + i] = off + loc[i];
    }
    if (tid == 1023) g_rptr[NN] = EP;
}
__global__ void k_fill() {
    int i = blockIdx.x * blockDim.x + threadIdx.x;
    if (i >= EP) return;
    int pos = atomicAdd(&g_woff[g_dst[i]], 1);
    g_csrc[pos] = g_src[i];
}

// ---------------- fused pre-pass: cvt(x) + W1T + W2T + fcwT ----------------
#define NB_CVT 6144
#define NB_W1  (192 * 24)
#define NB_W2  (24 * 192)
#define NB_FC  (24 * 48)
__device__ __forceinline__ void tr_tile(const float* __restrict__ in,
                                        __half* __restrict__ out,
                                        int R, int C, int bx, int by, int tid) {
    __shared__ float t[32][33];
    int tx = tid & 31, ty = tid >> 5;
    int x = bx * 32 + tx;
#pragma unroll
    for (int j = 0; j < 32; j += 8) {
        int y = by * 32 + ty + j;
        t[ty + j][tx] = in[(size_t)y * C + x];
    }
    __syncthreads();
    int ox = by * 32 + tx;
#pragma unroll
    for (int j = 0; j < 32; j += 8) {
        int oy = bx * 32 + ty + j;
        out[(size_t)oy * R + ox] = __float2half(t[tx][ty + j]);
    }
}
__global__ __launch_bounds__(256)
void k_preall(const float4* __restrict__ x4, __half2* __restrict__ xh2,
              const float* __restrict__ W1, __half* __restrict__ W1T,
              const float* __restrict__ W2, __half* __restrict__ W2T,
              const float* __restrict__ fcw, __half* __restrict__ fcwT) {
    int b = blockIdx.x, tid = threadIdx.x;
    if (b < NB_CVT) {
        size_t i = (size_t)b * 256 + tid;
        float4 v = x4[i];
        xh2[2 * i + 0] = __floats2half2_rn(v.x, v.y);
        xh2[2 * i + 1] = __floats2half2_rn(v.z, v.w);
        return;
    }
    b -= NB_CVT;
    if (b < NB_W1) { tr_tile(W1, W1T, DD, F1, b % 192, b / 192, tid); return; }
    b -= NB_W1;
    if (b < NB_W2) { tr_tile(W2, W2T, F1, CC, b % 24, b / 24, tid); return; }
    b -= NB_W2;
    tr_tile(fcw, fcwT, 2 * CC, CC, b % 24, b / 24, tid);
}

// ---------------- fp16 mma.sync GEMM (3-stage pipeline) --------------------
__device__ __forceinline__ void mma16816(float* c, const uint32_t* a,
                                         const uint32_t* b) {
    asm volatile(
        "mma.sync.aligned.m16n8k16.row.col.f32.f16.f16.f32 "
        "{%0,%1,%2,%3}, {%4,%5,%6,%7}, {%8,%9}, {%0,%1,%2,%3};"
        : "+f"(c[0]), "+f"(c[1]), "+f"(c[2]), "+f"(c[3])
        : "r"(a[0]), "r"(a[1]), "r"(a[2]), "r"(a[3]), "r"(b[0]), "r"(b[1]));
}
template <typename OutT, bool DOATT>
__global__ __launch_bounds__(GT, 2)
void hgemm(const __half* __restrict__ A, const __half* __restrict__ Bt,
           OutT* __restrict__ C, int Nd, int Kiter, int ldK, size_t partStride,
           const float* __restrict__ attA, const float* __restrict__ attD,
           float* __restrict__ outA, float* __restrict__ outD, int heads) {
    extern __shared__ __half hsm[];
    int tid = threadIdx.x;
    int wid = tid >> 5, lane = tid & 31;
    int wr = wid & 1, wc = wid >> 1;
    int g = lane >> 2, q = lane & 3;
    int row0 = blockIdx.y * BM, col0 = blockIdx.x * BN;
    int koff = blockIdx.z * Kiter;
    C += (size_t)blockIdx.z * partStride;
    const int NIT = Kiter / BK;
    uint32_t sbase = smem_u32(hsm);

    uint32_t a_off = (uint32_t)(((wr * 64 + (lane & 15)) * HPAD
                                 + ((lane & 16) ? 8 : 0)) * 2);
    uint32_t b_off = (uint32_t)(((wc * 32 + (lane & 7) + ((lane & 16) ? 8 : 0)) * HPAD
                                 + ((lane & 8) ? 8 : 0)) * 2);

    auto issue = [&](int s, int kt) {
        uint32_t as = sbase + (uint32_t)(s * 2 * HTILE) * 2u;
        uint32_t bs = as + (uint32_t)HTILE * 2u;
#pragma unroll
        for (int l = 0; l < 2; l++) {
            int p = tid + l * GT;
            int r = p >> 2, c0 = (p & 3) << 3;
            const __half* ga = A + (size_t)(row0 + r) * ldK + koff + kt + c0;
            uint32_t da = as + (uint32_t)(r * HPAD + c0) * 2u;
            asm volatile("cp.async.cg.shared.global [%0], [%1], 16;"
                         :: "r"(da), "l"(ga) : "memory");
            const __half* gb = Bt + (size_t)(col0 + r) * ldK + koff + kt + c0;
            uint32_t db = bs + (uint32_t)(r * HPAD + c0) * 2u;
            asm volatile("cp.async.cg.shared.global [%0], [%1], 16;"
                         :: "r"(db), "l"(gb) : "memory");
        }
        asm volatile("cp.async.commit_group;" ::: "memory");
    };

    float acc[4][4][4];
#pragma unroll
    for (int a = 0; a < 4; a++)
#pragma unroll
        for (int b = 0; b < 4; b++)
#pragma unroll
            for (int c = 0; c < 4; c++) acc[a][b][c] = 0.f;

    issue(0, 0);
    issue(1, BK);

    for (int i = 0; i < NIT; i++) {
        if (i + 2 < NIT) {
            issue((i + 2) % STG, (i + 2) * BK);
            asm volatile("cp.async.wait_group 2;" ::: "memory");
        } else {
            asm volatile("cp.async.wait_group 0;" ::: "memory");
        }
        __syncthreads();

        uint32_t as = sbase + (uint32_t)((i % STG) * 2 * HTILE) * 2u;
        uint32_t bs = as + (uint32_t)HTILE * 2u;
#pragma unroll
        for (int ki = 0; ki < 2; ki++) {
            uint32_t kb2 = (uint32_t)(ki * 16 * 2);
            uint32_t af[4][4], bf[4][2];
#pragma unroll
            for (int mi = 0; mi < 4; mi++) {
                uint32_t addr = as + a_off + (uint32_t)(mi * 16 * HPAD * 2) + kb2;
                LDSM4(af[mi][0], af[mi][1], af[mi][2], af[mi][3], addr);
            }
#pragma unroll
            for (int np = 0; np < 2; np++) {
                uint32_t addr = bs + b_off + (uint32_t)(np * 16 * HPAD * 2) + kb2;
                LDSM4(bf[2 * np][0], bf[2 * np][1],
                      bf[2 * np + 1][0], bf[2 * np + 1][1], addr);
            }
#pragma unroll
            for (int mi = 0; mi < 4; mi++)
#pragma unroll
                for (int ni = 0; ni < 4; ni++)
                    mma16816(acc[mi][ni], af[mi], bf[ni]);
        }
        __syncthreads();
    }

#pragma unroll
    for (int mi = 0; mi < 4; mi++) {
        int r0 = row0 + wr * 64 + mi * 16 + g;
#pragma unroll
        for (int ni = 0; ni < 4; ni++) {
            int col = col0 + wc * 32 + ni * 8 + q * 2;
            OutT* p0 = C + (size_t)r0 * Nd + col;
            OutT* p1 = p0 + (size_t)8 * Nd;
            if (sizeof(OutT) == 2) {
                *(__half2*)p0 = __floats2half2_rn(acc[mi][ni][0], acc[mi][ni][1]);
                *(__half2*)p1 = __floats2half2_rn(acc[mi][ni][2], acc[mi][ni][3]);
            } else {
                p0[0] = (OutT)acc[mi][ni][0]; p0[1] = (OutT)acc[mi][ni][1];
                p1[0] = (OutT)acc[mi][ni][2]; p1[1] = (OutT)acc[mi][ni][3];
            }
        }
    }

    if (DOATT) {
        // block lies entirely in one head (CC % BN == 0)
        int head = col0 / CC;
        float a0[4], a1[4], d0[4], d1[4];
#pragma unroll
        for (int ni = 0; ni < 4; ni++) {
            int lc = col0 + wc * 32 + ni * 8 + q * 2;
            a0[ni] = attA[lc]; a1[ni] = attA[lc + 1];
            d0[ni] = attD[lc]; d1[ni] = attD[lc + 1];
        }
#pragma unroll
        for (int mi = 0; mi < 4; mi++) {
            float sa0 = 0.f, sd0 = 0.f, sa1 = 0.f, sd1 = 0.f;
#pragma unroll
            for (int ni = 0; ni < 4; ni++) {
                sa0 += acc[mi][ni][0] * a0[ni] + acc[mi][ni][1] * a1[ni];
                sd0 += acc[mi][ni][0] * d0[ni] + acc[mi][ni][1] * d1[ni];
                sa1 += acc[mi][ni][2] * a0[ni] + acc[mi][ni][3] * a1[ni];
                sd1 += acc[mi][ni][2] * d0[ni] + acc[mi][ni][3] * d1[ni];
            }
#pragma unroll
            for (int o = 1; o < 4; o <<= 1) {
                sa0 += __shfl_xor_sync(~0u, sa0, o);
                sd0 += __shfl_xor_sync(~0u, sd0, o);
                sa1 += __shfl_xor_sync(~0u, sa1, o);
                sd1 += __shfl_xor_sync(~0u, sd1, o);
            }
            if (q == 0) {
                int r0 = row0 + wr * 64 + mi * 16 + g;
                atomicAdd(&outA[r0 * heads + head], sa0);
                atomicAdd(&outD[r0 * heads + head], sd0);
                atomicAdd(&outA[(r0 + 8) * heads + head], sa1);
                atomicAdd(&outD[(r0 + 8) * heads + head], sd1);
            }
        }
    }
}

// ---------------- split-K reduce + layer-2 attention dots ------------------
__global__ __launch_bounds__(256)
void k_red2att(const float* __restrict__ p0, const float* __restrict__ p1,
               const float* __restrict__ as2, const float* __restrict__ ad2,
               float* __restrict__ H2, float* __restrict__ asum,
               float* __restrict__ dsum) {
    int n = blockIdx.x, tid = threadIdx.x;
    int lane = tid & 31, w = tid >> 5;
    const float* a = p0 + (size_t)n * CC;
    const float* b = p1 + (size_t)n * CC;
    float s1 = 0.f, s2 = 0.f;
#pragma unroll
    for (int k = 0; k < 3; k++) {
        int c = tid + k * 256;
        float v = a[c] + b[c];
        H2[(size_t)n * CC + c] = v;
        s1 += v * as2[c];
        s2 += v * ad2[c];
    }
#pragma unroll
    for (int o = 16; o; o >>= 1) {
        s1 += __shfl_xor_sync(~0u, s1, o);
        s2 += __shfl_xor_sync(~0u, s2, o);
    }
    __shared__ float r1[8], r2[8];
    if (lane == 0) { r1[w] = s1; r2[w] = s2; }
    __syncthreads();
    if (tid == 0) {
        float t1 = 0.f, t2 = 0.f;
#pragma unroll
        for (int i = 0; i < 8; i++) { t1 += r1[i]; t2 += r2[i]; }
        asum[n] = t1;
        dsum[n] = t2;
    }
}

// ---------------- fused layer-1 aggregation (fp16, uint4 loads) ------------
#define CH1 64
__global__ __launch_bounds__(256)
void k_agg1(const uint4* __restrict__ H4, const float* __restrict__ asrc,
            const float* __restrict__ adst, const float* __restrict__ bias,
            uint4* __restrict__ out) {
    int d = blockIdx.x;
    int tid = threadIdx.x, wid = tid >> 5, lane = tid & 31;
    int beg = g_rptr[d], end = g_rptr[d + 1];
    __shared__ float s_m[H1H], s_den[H1H];
    __shared__ float s_coef[CH1 * H1H];
    __shared__ int s_src[CH1];

    {
        int h = wid;
        float adh = adst[d * H1H + h];
        float mx = -1e30f;
        for (int i = beg + lane; i < end; i += 32) {
            float v = asrc[g_csrc[i] * H1H + h] + adh;
            v = (v > 0.f) ? v : NEG_SLOPE * v;
            mx = fmaxf(mx, v);
        }
#pragma unroll
        for (int o = 16; o; o >>= 1) mx = fmaxf(mx, __shfl_xor_sync(~0u, mx, o));
        float sum = 0.f;
        for (int i = beg + lane; i < end; i += 32) {
            float v = asrc[g_csrc[i] * H1H + h] + adh;
            v = (v > 0.f) ? v : NEG_SLOPE * v;
            sum += expf(v - mx);
        }
#pragma unroll
        for (int o = 16; o; o >>= 1) sum += __shfl_xor_sync(~0u, sum, o);
        if (lane == 0) { s_m[h] = mx; s_den[h] = sum + 1e-16f; }
    }
    __syncthreads();

    int hk[3][4];
#pragma unroll
    for (int k = 0; k < 3; k++)
#pragma unroll
        for (int j = 0; j < 4; j++)
            hk[k][j] = (4 * (tid + k * 256) + j) / 384;
    float2 acc[3][4];
#pragma unroll
    for (int k = 0; k < 3; k++)
#pragma unroll
        for (int j = 0; j < 4; j++) acc[k][j] = make_float2(0.f, 0.f);

    for (int cb = beg; cb < end; cb += CH1) {
        int ch = min(CH1, end - cb);
        for (int i = tid; i < ch * H1H; i += 256) {
            int e = i >> 3, h = i & 7;
            int s = g_csrc[cb + e];
            float v = asrc[s * H1H + h] + adst[d * H1H + h];
            v = (v > 0.f) ? v : NEG_SLOPE * v;
            s_coef[i] = expf(v - s_m[h]) / s_den[h];
            if (h == 0) s_src[e] = s;
        }
        __syncthreads();
        for (int e = 0; e < ch; e++) {
            const uint4* hp = H4 + (size_t)s_src[e] * (F1 / 8);
            const float* cf = &s_coef[e * H1H];
#pragma unroll
            for (int k = 0; k < 3; k++) {
                uint4 u = hp[tid + k * 256];
                const __half2* hv = (const __half2*)&u;
#pragma unroll
                for (int j = 0; j < 4; j++) {
                    float2 v = __half22float2(hv[j]);
                    float c = cf[hk[k][j]];
                    acc[k][j].x += c * v.x;
                    acc[k][j].y += c * v.y;
                }
            }
        }
        __syncthreads();
    }
#pragma unroll
    for (int k = 0; k < 3; k++) {
        uint4 o;
        __half2* ov = (__half2*)&o;
#pragma unroll
        for (int j = 0; j < 4; j++) {
            int c = 2 * (4 * (tid + k * 256) + j);
            float v0 = acc[k][j].x + bias[c];
            float v1 = acc[k][j].y + bias[c + 1];
            v0 = (v0 > 0.f) ? v0 : expm1f(v0);
            v1 = (v1 > 0.f) ? v1 : expm1f(v1);
            ov[j] = __floats2half2_rn(v0, v1);
        }
        out[(size_t)d * (F1 / 8) + tid + k * 256] = o;
    }
}

// ---------------- fused layer-2 aggregation (fp32) ----------------
#define CH2 128
__global__ __launch_bounds__(256)
void k_agg2(const float* __restrict__ H, const float* __restrict__ asrc,
            const float* __restrict__ adst, float* __restrict__ out) {
    int d = blockIdx.x;
    int tid = threadIdx.x, wid = tid >> 5, lane = tid & 31;
    int beg = g_rptr[d], end = g_rptr[d + 1];
    __shared__ float s_m, s_den;
    __shared__ float s_coef[CH2];
    __shared__ int s_src[CH2];

    if (wid == 0) {
        float adh = adst[d];
        float mx = -1e30f;
        for (int i = beg + lane; i < end; i += 32) {
            float v = asrc[g_csrc[i]] + adh;
            v = (v > 0.f) ? v : NEG_SLOPE * v;
            mx = fmaxf(mx, v);
        }
#pragma unroll
        for (int o = 16; o; o >>= 1) mx = fmaxf(mx, __shfl_xor_sync(~0u, mx, o));
        float sum = 0.f;
        for (int i = beg + lane; i < end; i += 32) {
            float v = asrc[g_csrc[i]] + adh;
            v = (v > 0.f) ? v : NEG_SLOPE * v;
            sum += expf(v - mx);
        }
#pragma unroll
        for (int o = 16; o; o >>= 1) sum += __shfl_xor_sync(~0u, sum, o);
        if (lane == 0) { s_m = mx; s_den = sum + 1e-16f; }
    }
    __syncthreads();

    float acc[3] = {0.f, 0.f, 0.f};
    for (int cb = beg; cb < end; cb += CH2) {
        int ch = min(CH2, end - cb);
        for (int i = tid; i < ch; i += 256) {
            int s = g_csrc[cb + i];
            float v = asrc[s] + adst[d];
            v = (v > 0.f) ? v : NEG_SLOPE * v;
            s_coef[i] = expf(v - s_m) / s_den;
            s_src[i] = s;
        }
        __syncthreads();
        for (int e = 0; e < ch; e++) {
            const float* hp = H + (size_t)s_src[e] * CC;
            float cf = s_coef[e];
#pragma unroll
            for (int k = 0; k < 3; k++)
                acc[k] += cf * hp[tid + k * 256];
        }
        __syncthreads();
    }
#pragma unroll
    for (int k = 0; k < 3; k++)
        out[(size_t)d * CC + tid + k * 256] = acc[k];
}

// ---------------- gather + concat -> fp16 (adds b2) ----------------
__global__ void k_cath(const float* __restrict__ out2, const float* __restrict__ b2,
                       const float* __restrict__ x, __half* __restrict__ cat) {
    int i = blockIdx.x * blockDim.x + threadIdx.x;
    if (i >= MM * CC) return;
    int m = i / CC, c = i - m * CC;
    int idx = g_midx[m];
    cat[(size_t)m * (2 * CC) + c] = __float2half(out2[(size_t)idx * CC + c] + b2[c]);
    cat[(size_t)m * (2 * CC) + CC + c] = __float2half(x[(size_t)idx * DD + c]);
}

// ---------------- classifier (warp per row, adds fcb) ----------------
__global__ void k_cls(const float* __restrict__ fc, const float* __restrict__ fcb,
                      const float* __restrict__ w, const float* __restrict__ b,
                      float* __restrict__ out) {
    int gw = (blockIdx.x * blockDim.x + threadIdx.x) >> 5;
    int lane = threadIdx.x & 31;
    if (gw >= MM) return;
    const float* fp = fc + (size_t)gw * CC;
    float s0 = 0.f, s1 = 0.f;
    for (int c = lane; c < CC; c += 32) {
        float v = fp[c] + fcb[c];
        s0 += v * w[c * 2 + 0];
        s1 += v * w[c * 2 + 1];
    }
#pragma unroll
    for (int o = 16; o; o >>= 1) {
        s0 += __shfl_xor_sync(0xffffffffu, s0, o);
        s1 += __shfl_xor_sync(0xffffffffu, s1, o);
    }
    if (lane == 0) {
        out[gw * 2 + 0] = s0 + b[0];
        out[gw * 2 + 1] = s1 + b[1];
    }
}

// ---------------- launch ----------------
extern "C" void kernel_launch(void* const* d_in, const int* in_sizes, int n_in,
                              void* d_out, int out_size) {
    (void)in_sizes; (void)n_in; (void)out_size;
    const float* x   = (const float*)d_in[0];
    const void*  eix = d_in[1];
    const void*  mix = d_in[2];
    const float* W1  = (const float*)d_in[3];
    const float* as1 = (const float*)d_in[4];
    const float* ad1 = (const float*)d_in[5];
    const float* b1  = (const float*)d_in[6];
    const float* W2  = (const float*)d_in[7];
    const float* as2 = (const float*)d_in[8];
    const float* ad2 = (const float*)d_in[9];
    const float* b2  = (const float*)d_in[10];
    const float* fcw = (const float*)d_in[11];
    const float* fcb = (const float*)d_in[12];
    const float* clw = (const float*)d_in[13];
    const float* clb = (const float*)d_in[14];
    float* out = (float*)d_out;

    void *pH1h, *pOut1h, *pH2p, *pOut2, *pXh, *pAtt1, *pAs2, *pAd2;
    void *pCath, *pFc, *pW1T, *pW2T, *pFcwTh, *pCnt;
    cudaGetSymbolAddress(&pH1h, g_H1h);
    cudaGetSymbolAddress(&pOut1h, g_out1h);
    cudaGetSymbolAddress(&pH2p, g_H2p);
    cudaGetSymbolAddress(&pOut2, g_out2);
    cudaGetSymbolAddress(&pXh, g_xh);
    cudaGetSymbolAddress(&pAtt1, g_att1);
    cudaGetSymbolAddress(&pAs2, g_asrc2);
    cudaGetSymbolAddress(&pAd2, g_adst2);
    cudaGetSymbolAddress(&pCath, g_cath);
    cudaGetSymbolAddress(&pFc, g_fc);
    cudaGetSymbolAddress(&pW1T, g_W1T);
    cudaGetSymbolAddress(&pW2T, g_W2T);
    cudaGetSymbolAddress(&pFcwTh, g_fcwTh);
    cudaGetSymbolAddress(&pCnt, g_cnt);

    float* As1 = (float*)pAtt1;
    float* Ad1 = (float*)pAtt1 + (size_t)NN * H1H;
    float* H2  = (float*)pH2p;
    float* H2b = (float*)pH2p + (size_t)NN * CC;

    const int H_SMEM = STG * 2 * HTILE * 2;   // 61440 B
    cudaFuncSetAttribute(hgemm<__half, true>,
                         cudaFuncAttributeMaxDynamicSharedMemorySize, H_SMEM);
    cudaFuncSetAttribute(hgemm<float, false>,
                         cudaFuncAttributeMaxDynamicSharedMemorySize, H_SMEM);

    cudaMemsetAsync(pCnt, 0, NN * sizeof(int));
    cudaMemsetAsync(pAtt1, 0, (size_t)2 * NN * H1H * sizeof(float));
    k_prep<<<(EP + 255) / 256, 256>>>(eix, mix);
    k_scan<<<1, 1024>>>();
    k_fill<<<(EP + 255) / 256, 256>>>();

    k_preall<<<NB_CVT + NB_W1 + NB_W2 + NB_FC, 256>>>(
        (const float4*)x, (__half2*)pXh,
        W1, (__half*)pW1T, W2, (__half*)pW2T, fcw, (__half*)pFcwTh);

    // ---- layer 1 (att dots fused into epilogue) ----
    hgemm<__half, true><<<dim3(F1 / BN, NN / BM, 1), GT, H_SMEM>>>(
        (const __half*)pXh, (const __half*)pW1T, (__half*)pH1h,
        F1, DD, DD, 0, as1, ad1, As1, Ad1, H1H);
    k_agg1<<<NN, 256>>>((const uint4*)pH1h, As1, Ad1, b1, (uint4*)pOut1h);

    // ---- layer 2 (split-K=2; reduce fuses att dots) ----
    hgemm<float, false><<<dim3(CC / BN, NN / BM, 2), GT, H_SMEM>>>(
        (const __half*)pOut1h, (const __half*)pW2T, H2,
        CC, F1 / 2, F1, (size_t)NN * CC, nullptr, nullptr, nullptr, nullptr, 1);
    k_red2att<<<NN, 256>>>(H2, H2b, as2, ad2, H2, (float*)pAs2, (float*)pAd2);
    k_agg2<<<NN, 256>>>(H2, (const float*)pAs2, (const float*)pAd2, (float*)pOut2);

    // ---- head ----
    k_cath<<<(MM * CC + 255) / 256, 256>>>((const float*)pOut2, b2, x,
                                           (__half*)pCath);
    hgemm<float, false><<<dim3(CC / BN, MM / BM, 1), GT, H_SMEM>>>(
        (const __half*)pCath, (const __half*)pFcwTh, (float*)pFc,
        CC, 2 * CC, 2 * CC, 0, nullptr, nullptr, nullptr, nullptr, 1);
    k_cls<<<(MM * 32 + 255) / 256, 256>>>((const float*)pFc, fcb, clw, clb, out);
}

// round 16
// speedup vs baseline: 1.5705x; 1.0146x over previous
#include <cuda_runtime.h>
#include <cuda_fp16.h>
#include <math.h>
#include <stdint.h>

// Problem constants
#define NN 8192
#define EE 32768
#define EP 40960      // EE + NN self loops
#define DD 768
#define H1H 8
#define CC 768
#define F1 6144       // H1H * CC
#define MM 2048
#define NEG_SLOPE 0.2f

// fp16 GEMM (128x128 tile, 256 threads, 3-stage, 2 CTAs/SM) -- FROZEN CONFIG
#define BM 128
#define BN 128
#define BK 32
#define GT 256
#define STG 3
#define HPAD 40
#define HTILE (128 * HPAD)

// ---------------- scratch (device globals) ----------------
__device__ __half g_H1h[(size_t)NN * F1];
__device__ __half g_out1h[(size_t)NN * F1];
__device__ float  g_H2p[(size_t)2 * NN * CC];   // split-K partials; [0] becomes H2
__device__ float  g_out2[(size_t)NN * CC];
__device__ __half g_xh[(size_t)NN * DD];
__device__ float g_att1[2 * NN * H1H];          // [asrc | adst], one memset
__device__ float g_asrc2[NN], g_adst2[NN];
__device__ int g_src[EP], g_dst[EP], g_midx[MM];
__device__ __half g_cath[(size_t)MM * 2 * CC];
__device__ __half g_W1T[(size_t)F1 * DD];
__device__ __half g_W2T[(size_t)CC * F1];
__device__ __half g_fcwTh[(size_t)CC * 2 * CC];
// CSR
__device__ int g_cnt[NN];
__device__ int g_rptr[NN + 1];
__device__ int g_woff[NN];
__device__ int g_csrc[EP];

// ---------------- helpers ----------------
__device__ __forceinline__ int load_idx(const void* p, long long i, int is64) {
    if (is64) return (int)((const long long*)p)[i];
    return ((const int*)p)[i];
}
__device__ __forceinline__ uint32_t smem_u32(const void* p) {
    uint32_t a;
    asm("{ .reg .u64 t; cvta.to.shared.u64 t, %1; cvt.u32.u64 %0, t; }"
        : "=r"(a) : "l"(p));
    return a;
}

#define LDSM4(r0, r1, r2, r3, addr) \
    asm volatile("ldmatrix.sync.aligned.m8n8.x4.shared.b16 {%0,%1,%2,%3}, [%4];" \
                 : "=r"(r0), "=r"(r1), "=r"(r2), "=r"(r3) : "r"(addr))

// ---------------- prep: dtype detect + index decode + degree count ---------
__global__ void k_prep(const void* ebuf, const void* mbuf) {
    const unsigned* eu = (const unsigned*)ebuf;
    const unsigned* mu = (const unsigned*)mbuf;
    int fe = 1, fm = 1;
#pragma unroll
    for (int i = 0; i < 16; i++) if (eu[2 * i + 1] != 0u) { fe = 0; break; }
#pragma unroll
    for (int i = 0; i < 16; i++) if (mu[2 * i + 1] != 0u) { fm = 0; break; }

    int i = blockIdx.x * blockDim.x + threadIdx.x;
    if (i < EP) {
        int s, d;
        if (i < EE) {
            s = load_idx(ebuf, i, fe);
            d = load_idx(ebuf, (long long)EE + i, fe);
        } else {
            s = i - EE;
            d = i - EE;
        }
        g_src[i] = s;
        g_dst[i] = d;
        atomicAdd(&g_cnt[d], 1);
    }
    if (i < MM) g_midx[i] = load_idx(mbuf, i, fm);
}

// ---------------- CSR build ----------------
__global__ void k_scan() {
    __shared__ int wsum[32];
    int tid = threadIdx.x;
    int lane = tid & 31, w = tid >> 5;
    int base = tid * 8;
    int loc[8];
    int s = 0;
#pragma unroll
    for (int i = 0; i < 8; i++) { loc[i] = s; s += g_cnt[base + i]; }
    int inc = s;
#pragma unroll
    for (int o = 1; o < 32; o <<= 1) {
        int v = __shfl_up_sync(~0u, inc, o);
        if (lane >= o) inc += v;
    }
    if (lane == 31) wsum[w] = inc;
    __syncthreads();
    if (w == 0) {
        int v = wsum[lane];
#pragma unroll
        for (int o = 1; o < 32; o <<= 1) {
            int t = __shfl_up_sync(~0u, v, o);
            if (lane >= o) v += t;
        }
        wsum[lane] = v;
    }
    __syncthreads();
    int off = inc - s + (w ? wsum[w - 1] : 0);
#pragma unroll
    for (int i = 0; i < 8; i++) {
        g_rptr[base + i] = off + loc[i];
        g_woff[base + i] = off + loc[i];
    }
    if (tid == 1023) g_rptr[NN] = EP;
}
__global__ void k_fill() {
    int i = blockIdx.x * blockDim.x + threadIdx.x;
    if (i >= EP) return;
    int pos = atomicAdd(&g_woff[g_dst[i]], 1);
    g_csrc[pos] = g_src[i];
}

// ---------------- fused pre-pass: cvt(x) + W1T + W2T + fcwT ----------------
#define NB_CVT 6144
#define NB_W1  (192 * 24)
#define NB_W2  (24 * 192)
#define NB_FC  (24 * 48)
__device__ __forceinline__ void tr_tile(const float* __restrict__ in,
                                        __half* __restrict__ out,
                                        int R, int C, int bx, int by, int tid) {
    __shared__ float t[32][33];
    int tx = tid & 31, ty = tid >> 5;
    int x = bx * 32 + tx;
#pragma unroll
    for (int j = 0; j < 32; j += 8) {
        int y = by * 32 + ty + j;
        t[ty + j][tx] = in[(size_t)y * C + x];
    }
    __syncthreads();
    int ox = by * 32 + tx;
#pragma unroll
    for (int j = 0; j < 32; j += 8) {
        int oy = bx * 32 + ty + j;
        out[(size_t)oy * R + ox] = __float2half(t[tx][ty + j]);
    }
}
__global__ __launch_bounds__(256)
void k_preall(const float4* __restrict__ x4, __half2* __restrict__ xh2,
              const float* __restrict__ W1, __half* __restrict__ W1T,
              const float* __restrict__ W2, __half* __restrict__ W2T,
              const float* __restrict__ fcw, __half* __restrict__ fcwT) {
    int b = blockIdx.x, tid = threadIdx.x;
    if (b < NB_CVT) {
        size_t i = (size_t)b * 256 + tid;
        float4 v = x4[i];
        xh2[2 * i + 0] = __floats2half2_rn(v.x, v.y);
        xh2[2 * i + 1] = __floats2half2_rn(v.z, v.w);
        return;
    }
    b -= NB_CVT;
    if (b < NB_W1) { tr_tile(W1, W1T, DD, F1, b % 192, b / 192, tid); return; }
    b -= NB_W1;
    if (b < NB_W2) { tr_tile(W2, W2T, F1, CC, b % 24, b / 24, tid); return; }
    b -= NB_W2;
    tr_tile(fcw, fcwT, 2 * CC, CC, b % 24, b / 24, tid);
}

// ---------------- classifier init: out[m][j] = clb[j] + dot(fcb, clw[:,j]) --
__global__ __launch_bounds__(256)
void k_clsinit(const float* __restrict__ fcb, const float* __restrict__ clw,
               const float* __restrict__ clb, float* __restrict__ out) {
    __shared__ float r0[8], r1[8];
    int tid = threadIdx.x, lane = tid & 31, w = tid >> 5;
    float s0 = 0.f, s1 = 0.f;
    for (int c = tid; c < CC; c += 256) {
        float v = fcb[c];
        s0 += v * clw[c * 2 + 0];
        s1 += v * clw[c * 2 + 1];
    }
#pragma unroll
    for (int o = 16; o; o >>= 1) {
        s0 += __shfl_xor_sync(~0u, s0, o);
        s1 += __shfl_xor_sync(~0u, s1, o);
    }
    if (lane == 0) { r0[w] = s0; r1[w] = s1; }
    __syncthreads();
    float c0 = 0.f, c1 = 0.f;
#pragma unroll
    for (int i = 0; i < 8; i++) { c0 += r0[i]; c1 += r1[i]; }
    c0 += clb[0]; c1 += clb[1];
    for (int m = tid; m < MM; m += 256) {
        out[m * 2 + 0] = c0;
        out[m * 2 + 1] = c1;
    }
}

// ---------------- fp16 mma.sync GEMM (3-stage pipeline) --------------------
// MODE 0: plain C store.  MODE 1: C store + fused att dots (attA/attD ->
// outA/outD, heads).  MODE 2: no C store; fused classifier (attA = clw,
// outA = out[M,2], atomicAdd partial dot products).
__device__ __forceinline__ void mma16816(float* c, const uint32_t* a,
                                         const uint32_t* b) {
    asm volatile(
        "mma.sync.aligned.m16n8k16.row.col.f32.f16.f16.f32 "
        "{%0,%1,%2,%3}, {%4,%5,%6,%7}, {%8,%9}, {%0,%1,%2,%3};"
        : "+f"(c[0]), "+f"(c[1]), "+f"(c[2]), "+f"(c[3])
        : "r"(a[0]), "r"(a[1]), "r"(a[2]), "r"(a[3]), "r"(b[0]), "r"(b[1]));
}
template <typename OutT, int MODE>
__global__ __launch_bounds__(GT, 2)
void hgemm(const __half* __restrict__ A, const __half* __restrict__ Bt,
           OutT* __restrict__ C, int Nd, int Kiter, int ldK, size_t partStride,
           const float* __restrict__ attA, const float* __restrict__ attD,
           float* __restrict__ outA, float* __restrict__ outD, int heads) {
    extern __shared__ __half hsm[];
    int tid = threadIdx.x;
    int wid = tid >> 5, lane = tid & 31;
    int wr = wid & 1, wc = wid >> 1;
    int g = lane >> 2, q = lane & 3;
    int row0 = blockIdx.y * BM, col0 = blockIdx.x * BN;
    int koff = blockIdx.z * Kiter;
    C += (size_t)blockIdx.z * partStride;
    const int NIT = Kiter / BK;
    uint32_t sbase = smem_u32(hsm);

    uint32_t a_off = (uint32_t)(((wr * 64 + (lane & 15)) * HPAD
                                 + ((lane & 16) ? 8 : 0)) * 2);
    uint32_t b_off = (uint32_t)(((wc * 32 + (lane & 7) + ((lane & 16) ? 8 : 0)) * HPAD
                                 + ((lane & 8) ? 8 : 0)) * 2);

    auto issue = [&](int s, int kt) {
        uint32_t as = sbase + (uint32_t)(s * 2 * HTILE) * 2u;
        uint32_t bs = as + (uint32_t)HTILE * 2u;
#pragma unroll
        for (int l = 0; l < 2; l++) {
            int p = tid + l * GT;
            int r = p >> 2, c0 = (p & 3) << 3;
            const __half* ga = A + (size_t)(row0 + r) * ldK + koff + kt + c0;
            uint32_t da = as + (uint32_t)(r * HPAD + c0) * 2u;
            asm volatile("cp.async.cg.shared.global [%0], [%1], 16;"
                         :: "r"(da), "l"(ga) : "memory");
            const __half* gb = Bt + (size_t)(col0 + r) * ldK + koff + kt + c0;
            uint32_t db = bs + (uint32_t)(r * HPAD + c0) * 2u;
            asm volatile("cp.async.cg.shared.global [%0], [%1], 16;"
                         :: "r"(db), "l"(gb) : "memory");
        }
        asm volatile("cp.async.commit_group;" ::: "memory");
    };

    float acc[4][4][4];
#pragma unroll
    for (int a = 0; a < 4; a++)
#pragma unroll
        for (int b = 0; b < 4; b++)
#pragma unroll
            for (int c = 0; c < 4; c++) acc[a][b][c] = 0.f;

    issue(0, 0);
    issue(1, BK);

    for (int i = 0; i < NIT; i++) {
        if (i + 2 < NIT) {
            issue((i + 2) % STG, (i + 2) * BK);
            asm volatile("cp.async.wait_group 2;" ::: "memory");
        } else {
            asm volatile("cp.async.wait_group 0;" ::: "memory");
        }
        __syncthreads();

        uint32_t as = sbase + (uint32_t)((i % STG) * 2 * HTILE) * 2u;
        uint32_t bs = as + (uint32_t)HTILE * 2u;
#pragma unroll
        for (int ki = 0; ki < 2; ki++) {
            uint32_t kb2 = (uint32_t)(ki * 16 * 2);
            uint32_t af[4][4], bf[4][2];
#pragma unroll
            for (int mi = 0; mi < 4; mi++) {
                uint32_t addr = as + a_off + (uint32_t)(mi * 16 * HPAD * 2) + kb2;
                LDSM4(af[mi][0], af[mi][1], af[mi][2], af[mi][3], addr);
            }
#pragma unroll
            for (int np = 0; np < 2; np++) {
                uint32_t addr = bs + b_off + (uint32_t)(np * 16 * HPAD * 2) + kb2;
                LDSM4(bf[2 * np][0], bf[2 * np][1],
                      bf[2 * np + 1][0], bf[2 * np + 1][1], addr);
            }
#pragma unroll
            for (int mi = 0; mi < 4; mi++)
#pragma unroll
                for (int ni = 0; ni < 4; ni++)
                    mma16816(acc[mi][ni], af[mi], bf[ni]);
        }
        __syncthreads();
    }

    if (MODE != 2) {
#pragma unroll
        for (int mi = 0; mi < 4; mi++) {
            int r0 = row0 + wr * 64 + mi * 16 + g;
#pragma unroll
            for (int ni = 0; ni < 4; ni++) {
                int col = col0 + wc * 32 + ni * 8 + q * 2;
                OutT* p0 = C + (size_t)r0 * Nd + col;
                OutT* p1 = p0 + (size_t)8 * Nd;
                if (sizeof(OutT) == 2) {
                    *(__half2*)p0 = __floats2half2_rn(acc[mi][ni][0], acc[mi][ni][1]);
                    *(__half2*)p1 = __floats2half2_rn(acc[mi][ni][2], acc[mi][ni][3]);
                } else {
                    p0[0] = (OutT)acc[mi][ni][0]; p0[1] = (OutT)acc[mi][ni][1];
                    p1[0] = (OutT)acc[mi][ni][2]; p1[1] = (OutT)acc[mi][ni][3];
                }
            }
        }
    }

    if (MODE == 1) {
        // block lies entirely in one head (CC % BN == 0)
        int head = col0 / CC;
        float a0[4], a1[4], d0[4], d1[4];
#pragma unroll
        for (int ni = 0; ni < 4; ni++) {
            int lc = col0 + wc * 32 + ni * 8 + q * 2;
            a0[ni] = attA[lc]; a1[ni] = attA[lc + 1];
            d0[ni] = attD[lc]; d1[ni] = attD[lc + 1];
        }
#pragma unroll
        for (int mi = 0; mi < 4; mi++) {
            float sa0 = 0.f, sd0 = 0.f, sa1 = 0.f, sd1 = 0.f;
#pragma unroll
            for (int ni = 0; ni < 4; ni++) {
                sa0 += acc[mi][ni][0] * a0[ni] + acc[mi][ni][1] * a1[ni];
                sd0 += acc[mi][ni][0] * d0[ni] + acc[mi][ni][1] * d1[ni];
                sa1 += acc[mi][ni][2] * a0[ni] + acc[mi][ni][3] * a1[ni];
                sd1 += acc[mi][ni][2] * d0[ni] + acc[mi][ni][3] * d1[ni];
            }
#pragma unroll
            for (int o = 1; o < 4; o <<= 1) {
                sa0 += __shfl_xor_sync(~0u, sa0, o);
                sd0 += __shfl_xor_sync(~0u, sd0, o);
                sa1 += __shfl_xor_sync(~0u, sa1, o);
                sd1 += __shfl_xor_sync(~0u, sd1, o);
            }
            if (q == 0) {
                int r0 = row0 + wr * 64 + mi * 16 + g;
                atomicAdd(&outA[r0 * heads + head], sa0);
                atomicAdd(&outD[r0 * heads + head], sd0);
                atomicAdd(&outA[(r0 + 8) * heads + head], sa1);
                atomicAdd(&outD[(r0 + 8) * heads + head], sd1);
            }
        }
    }

    if (MODE == 2) {
        // fused classifier: attA = clw [CC,2]; outA = out [M,2]
        float w0[4], w1[4], v0[4], v1[4];
#pragma unroll
        for (int ni = 0; ni < 4; ni++) {
            int c = col0 + wc * 32 + ni * 8 + q * 2;
            w0[ni] = attA[c * 2 + 0];       // clw[c][0]
            v0[ni] = attA[c * 2 + 1];       // clw[c][1]
            w1[ni] = attA[(c + 1) * 2 + 0]; // clw[c+1][0]
            v1[ni] = attA[(c + 1) * 2 + 1]; // clw[c+1][1]
        }
#pragma unroll
        for (int mi = 0; mi < 4; mi++) {
            float sa0 = 0.f, sb0 = 0.f, sa1 = 0.f, sb1 = 0.f;
#pragma unroll
            for (int ni = 0; ni < 4; ni++) {
                sa0 += acc[mi][ni][0] * w0[ni] + acc[mi][ni][1] * w1[ni];
                sb0 += acc[mi][ni][0] * v0[ni] + acc[mi][ni][1] * v1[ni];
                sa1 += acc[mi][ni][2] * w0[ni] + acc[mi][ni][3] * w1[ni];
                sb1 += acc[mi][ni][2] * v0[ni] + acc[mi][ni][3] * v1[ni];
            }
#pragma unroll
            for (int o = 1; o < 4; o <<= 1) {
                sa0 += __shfl_xor_sync(~0u, sa0, o);
                sb0 += __shfl_xor_sync(~0u, sb0, o);
                sa1 += __shfl_xor_sync(~0u, sa1, o);
                sb1 += __shfl_xor_sync(~0u, sb1, o);
            }
            if (q == 0) {
                int r0 = row0 + wr * 64 + mi * 16 + g;
                atomicAdd(&outA[r0 * 2 + 0], sa0);
                atomicAdd(&outA[r0 * 2 + 1], sb0);
                atomicAdd(&outA[(r0 + 8) * 2 + 0], sa1);
                atomicAdd(&outA[(r0 + 8) * 2 + 1], sb1);
            }
        }
    }
}

// ---------------- split-K reduce + layer-2 attention dots ------------------
__global__ __launch_bounds__(256)
void k_red2att(const float* __restrict__ p0, const float* __restrict__ p1,
               const float* __restrict__ as2, const float* __restrict__ ad2,
               float* __restrict__ H2, float* __restrict__ asum,
               float* __restrict__ dsum) {
    int n = blockIdx.x, tid = threadIdx.x;
    int lane = tid & 31, w = tid >> 5;
    const float* a = p0 + (size_t)n * CC;
    const float* b = p1 + (size_t)n * CC;
    float s1 = 0.f, s2 = 0.f;
#pragma unroll
    for (int k = 0; k < 3; k++) {
        int c = tid + k * 256;
        float v = a[c] + b[c];
        H2[(size_t)n * CC + c] = v;
        s1 += v * as2[c];
        s2 += v * ad2[c];
    }
#pragma unroll
    for (int o = 16; o; o >>= 1) {
        s1 += __shfl_xor_sync(~0u, s1, o);
        s2 += __shfl_xor_sync(~0u, s2, o);
    }
    __shared__ float r1[8], r2[8];
    if (lane == 0) { r1[w] = s1; r2[w] = s2; }
    __syncthreads();
    if (tid == 0) {
        float t1 = 0.f, t2 = 0.f;
#pragma unroll
        for (int i = 0; i < 8; i++) { t1 += r1[i]; t2 += r2[i]; }
        asum[n] = t1;
        dsum[n] = t2;
    }
}

// ---------------- fused layer-1 aggregation (fp16, uint4 loads) ------------
#define CH1 64
__global__ __launch_bounds__(256)
void k_agg1(const uint4* __restrict__ H4, const float* __restrict__ asrc,
            const float* __restrict__ adst, const float* __restrict__ bias,
            uint4* __restrict__ out) {
    int d = blockIdx.x;
    int tid = threadIdx.x, wid = tid >> 5, lane = tid & 31;
    int beg = g_rptr[d], end = g_rptr[d + 1];
    __shared__ float s_m[H1H], s_den[H1H];
    __shared__ float s_coef[CH1 * H1H];
    __shared__ int s_src[CH1];

    {
        int h = wid;
        float adh = adst[d * H1H + h];
        float mx = -1e30f;
        for (int i = beg + lane; i < end; i += 32) {
            float v = asrc[g_csrc[i] * H1H + h] + adh;
            v = (v > 0.f) ? v : NEG_SLOPE * v;
            mx = fmaxf(mx, v);
        }
#pragma unroll
        for (int o = 16; o; o >>= 1) mx = fmaxf(mx, __shfl_xor_sync(~0u, mx, o));
        float sum = 0.f;
        for (int i = beg + lane; i < end; i += 32) {
            float v = asrc[g_csrc[i] * H1H + h] + adh;
            v = (v > 0.f) ? v : NEG_SLOPE * v;
            sum += expf(v - mx);
        }
#pragma unroll
        for (int o = 16; o; o >>= 1) sum += __shfl_xor_sync(~0u, sum, o);
        if (lane == 0) { s_m[h] = mx; s_den[h] = sum + 1e-16f; }
    }
    __syncthreads();

    int hk[3][4];
#pragma unroll
    for (int k = 0; k < 3; k++)
#pragma unroll
        for (int j = 0; j < 4; j++)
            hk[k][j] = (4 * (tid + k * 256) + j) / 384;
    float2 acc[3][4];
#pragma unroll
    for (int k = 0; k < 3; k++)
#pragma unroll
        for (int j = 0; j < 4; j++) acc[k][j] = make_float2(0.f, 0.f);

    for (int cb = beg; cb < end; cb += CH1) {
        int ch = min(CH1, end - cb);
        for (int i = tid; i < ch * H1H; i += 256) {
            int e = i >> 3, h = i & 7;
            int s = g_csrc[cb + e];
            float v = asrc[s * H1H + h] + adst[d * H1H + h];
            v = (v > 0.f) ? v : NEG_SLOPE * v;
            s_coef[i] = expf(v - s_m[h]) / s_den[h];
            if (h == 0) s_src[e] = s;
        }
        __syncthreads();
        for (int e = 0; e < ch; e++) {
            const uint4* hp = H4 + (size_t)s_src[e] * (F1 / 8);
            const float* cf = &s_coef[e * H1H];
#pragma unroll
            for (int k = 0; k < 3; k++) {
                uint4 u = hp[tid + k * 256];
                const __half2* hv = (const __half2*)&u;
#pragma unroll
                for (int j = 0; j < 4; j++) {
                    float2 v = __half22float2(hv[j]);
                    float c = cf[hk[k][j]];
                    acc[k][j].x += c * v.x;
                    acc[k][j].y += c * v.y;
                }
            }
        }
        __syncthreads();
    }
#pragma unroll
    for (int k = 0; k < 3; k++) {
        uint4 o;
        __half2* ov = (__half2*)&o;
#pragma unroll
        for (int j = 0; j < 4; j++) {
            int c = 2 * (4 * (tid + k * 256) + j);
            float v0 = acc[k][j].x + bias[c];
            float v1 = acc[k][j].y + bias[c + 1];
            v0 = (v0 > 0.f) ? v0 : expm1f(v0);
            v1 = (v1 > 0.f) ? v1 : expm1f(v1);
            ov[j] = __floats2half2_rn(v0, v1);
        }
        out[(size_t)d * (F1 / 8) + tid + k * 256] = o;
    }
}

// ---------------- fused layer-2 aggregation (fp32) ----------------
#define CH2 128
__global__ __launch_bounds__(256)
void k_agg2(const float* __restrict__ H, const float* __restrict__ asrc,
            const float* __restrict__ adst, float* __restrict__ out) {
    int d = blockIdx.x;
    int tid = threadIdx.x, wid = tid >> 5, lane = tid & 31;
    int beg = g_rptr[d], end = g_rptr[d + 1];
    __shared__ float s_m, s_den;
    __shared__ float s_coef[CH2];
    __shared__ int s_src[CH2];

    if (wid == 0) {
        float adh = adst[d];
        float mx = -1e30f;
        for (int i = beg + lane; i < end; i += 32) {
            float v = asrc[g_csrc[i]] + adh;
            v = (v > 0.f) ? v : NEG_SLOPE * v;
            mx = fmaxf(mx, v);
        }
#pragma unroll
        for (int o = 16; o; o >>= 1) mx = fmaxf(mx, __shfl_xor_sync(~0u, mx, o));
        float sum = 0.f;
        for (int i = beg + lane; i < end; i += 32) {
            float v = asrc[g_csrc[i]] + adh;
            v = (v > 0.f) ? v : NEG_SLOPE * v;
            sum += expf(v - mx);
        }
#pragma unroll
        for (int o = 16; o; o >>= 1) sum += __shfl_xor_sync(~0u, sum, o);
        if (lane == 0) { s_m = mx; s_den = sum + 1e-16f; }
    }
    __syncthreads();

    float acc[3] = {0.f, 0.f, 0.f};
    for (int cb = beg; cb < end; cb += CH2) {
        int ch = min(CH2, end - cb);
        for (int i = tid; i < ch; i += 256) {
            int s = g_csrc[cb + i];
            float v = asrc[s] + adst[d];
            v = (v > 0.f) ? v : NEG_SLOPE * v;
            s_coef[i] = expf(v - s_m) / s_den;
            s_src[i] = s;
        }
        __syncthreads();
        for (int e = 0; e < ch; e++) {
            const float* hp = H + (size_t)s_src[e] * CC;
            float cf = s_coef[e];
#pragma unroll
            for (int k = 0; k < 3; k++)
                acc[k] += cf * hp[tid + k * 256];
        }
        __syncthreads();
    }
#pragma unroll
    for (int k = 0; k < 3; k++)
        out[(size_t)d * CC + tid + k * 256] = acc[k];
}

// ---------------- gather + concat -> fp16 (adds b2) ----------------
__global__ void k_cath(const float* __restrict__ out2, const float* __restrict__ b2,
                       const float* __restrict__ x, __half* __restrict__ cat) {
    int i = blockIdx.x * blockDim.x + threadIdx.x;
    if (i >= MM * CC) return;
    int m = i / CC, c = i - m * CC;
    int idx = g_midx[m];
    cat[(size_t)m * (2 * CC) + c] = __float2half(out2[(size_t)idx * CC + c] + b2[c]);
    cat[(size_t)m * (2 * CC) + CC + c] = __float2half(x[(size_t)idx * DD + c]);
}

// ---------------- launch ----------------
extern "C" void kernel_launch(void* const* d_in, const int* in_sizes, int n_in,
                              void* d_out, int out_size) {
    (void)in_sizes; (void)n_in; (void)out_size;
    const float* x   = (const float*)d_in[0];
    const void*  eix = d_in[1];
    const void*  mix = d_in[2];
    const float* W1  = (const float*)d_in[3];
    const float* as1 = (const float*)d_in[4];
    const float* ad1 = (const float*)d_in[5];
    const float* b1  = (const float*)d_in[6];
    const float* W2  = (const float*)d_in[7];
    const float* as2 = (const float*)d_in[8];
    const float* ad2 = (const float*)d_in[9];
    const float* b2  = (const float*)d_in[10];
    const float* fcw = (const float*)d_in[11];
    const float* fcb = (const float*)d_in[12];
    const float* clw = (const float*)d_in[13];
    const float* clb = (const float*)d_in[14];
    float* out = (float*)d_out;

    void *pH1h, *pOut1h, *pH2p, *pOut2, *pXh, *pAtt1, *pAs2, *pAd2;
    void *pCath, *pW1T, *pW2T, *pFcwTh, *pCnt;
    cudaGetSymbolAddress(&pH1h, g_H1h);
    cudaGetSymbolAddress(&pOut1h, g_out1h);
    cudaGetSymbolAddress(&pH2p, g_H2p);
    cudaGetSymbolAddress(&pOut2, g_out2);
    cudaGetSymbolAddress(&pXh, g_xh);
    cudaGetSymbolAddress(&pAtt1, g_att1);
    cudaGetSymbolAddress(&pAs2, g_asrc2);
    cudaGetSymbolAddress(&pAd2, g_adst2);
    cudaGetSymbolAddress(&pCath, g_cath);
    cudaGetSymbolAddress(&pW1T, g_W1T);
    cudaGetSymbolAddress(&pW2T, g_W2T);
    cudaGetSymbolAddress(&pFcwTh, g_fcwTh);
    cudaGetSymbolAddress(&pCnt, g_cnt);

    float* As1 = (float*)pAtt1;
    float* Ad1 = (float*)pAtt1 + (size_t)NN * H1H;
    float* H2  = (float*)pH2p;
    float* H2b = (float*)pH2p + (size_t)NN * CC;

    const int H_SMEM = STG * 2 * HTILE * 2;   // 61440 B
    cudaFuncSetAttribute(hgemm<__half, 1>,
                         cudaFuncAttributeMaxDynamicSharedMemorySize, H_SMEM);
    cudaFuncSetAttribute(hgemm<float, 0>,
                         cudaFuncAttributeMaxDynamicSharedMemorySize, H_SMEM);
    cudaFuncSetAttribute(hgemm<float, 2>,
                         cudaFuncAttributeMaxDynamicSharedMemorySize, H_SMEM);

    cudaMemsetAsync(pCnt, 0, NN * sizeof(int));
    cudaMemsetAsync(pAtt1, 0, (size_t)2 * NN * H1H * sizeof(float));
    k_prep<<<(EP + 255) / 256, 256>>>(eix, mix);
    k_scan<<<1, 1024>>>();
    k_fill<<<(EP + 255) / 256, 256>>>();

    k_preall<<<NB_CVT + NB_W1 + NB_W2 + NB_FC, 256>>>(
        (const float4*)x, (__half2*)pXh,
        W1, (__half*)pW1T, W2, (__half*)pW2T, fcw, (__half*)pFcwTh);

    // ---- layer 1 (att dots fused into epilogue) ----
    hgemm<__half, 1><<<dim3(F1 / BN, NN / BM, 1), GT, H_SMEM>>>(
        (const __half*)pXh, (const __half*)pW1T, (__half*)pH1h,
        F1, DD, DD, 0, as1, ad1, As1, Ad1, H1H);
    k_agg1<<<NN, 256>>>((const uint4*)pH1h, As1, Ad1, b1, (uint4*)pOut1h);

    // ---- layer 2 (split-K=2; reduce fuses att dots) ----
    hgemm<float, 0><<<dim3(CC / BN, NN / BM, 2), GT, H_SMEM>>>(
        (const __half*)pOut1h, (const __half*)pW2T, H2,
        CC, F1 / 2, F1, (size_t)NN * CC, nullptr, nullptr, nullptr, nullptr, 1);
    k_red2att<<<NN, 256>>>(H2, H2b, as2, ad2, H2, (float*)pAs2, (float*)pAd2);
    k_agg2<<<NN, 256>>>(H2, (const float*)pAs2, (const float*)pAd2, (float*)pOut2);

    // ---- head: concat -> fc GEMM with fused classifier ----
    k_cath<<<(MM * CC + 255) / 256, 256>>>((const float*)pOut2, b2, x,
                                           (__half*)pCath);
    k_clsinit<<<1, 256>>>(fcb, clw, clb, out);
    hgemm<float, 2><<<dim3(CC / BN, MM / BM, 1), GT, H_SMEM>>>(
        (const __half*)pCath, (const __half*)pFcwTh, (float*)nullptr,
        CC, 2 * CC, 2 * CC, 0, clw, nullptr, out, nullptr, 1);
}

// round 17
// speedup vs baseline: 1.5995x; 1.0185x over previous
#include <cuda_runtime.h>
#include <cuda_fp16.h>
#include <math.h>
#include <stdint.h>

// Problem constants
#define NN 8192
#define EE 32768
#define EP 40960      // EE + NN self loops
#define DD 768
#define H1H 8
#define CC 768
#define F1 6144       // H1H * CC
#define MM 2048
#define NEG_SLOPE 0.2f

// fp16 GEMM (128x128 tile, 256 threads, 3-stage, 2 CTAs/SM) -- FROZEN CONFIG
#define BM 128
#define BN 128
#define BK 32
#define GT 256
#define STG 3
#define HPAD 40
#define HTILE (128 * HPAD)

// ---------------- scratch (device globals) ----------------
__device__ __half g_H1h[(size_t)NN * F1];
__device__ __half g_out1h[(size_t)NN * F1];
__device__ float  g_H2p[(size_t)2 * NN * CC];   // split-K partials; [0] becomes H2
__device__ __half g_xh[(size_t)NN * DD];
__device__ float g_att1[2 * NN * H1H];          // [asrc | adst], one memset
__device__ float g_asrc2[NN], g_adst2[NN];
__device__ int g_src[EP], g_dst[EP], g_midx[MM];
__device__ __half g_cath[(size_t)MM * 2 * CC];
__device__ __half g_W1T[(size_t)F1 * DD];
__device__ __half g_W2T[(size_t)CC * F1];
__device__ __half g_fcwTh[(size_t)CC * 2 * CC];
// CSR
__device__ int g_cnt[NN];
__device__ int g_rptr[NN + 1];
__device__ int g_woff[NN];
__device__ int g_csrc[EP];

// ---------------- helpers ----------------
__device__ __forceinline__ int load_idx(const void* p, long long i, int is64) {
    if (is64) return (int)((const long long*)p)[i];
    return ((const int*)p)[i];
}
__device__ __forceinline__ uint32_t smem_u32(const void* p) {
    uint32_t a;
    asm("{ .reg .u64 t; cvta.to.shared.u64 t, %1; cvt.u32.u64 %0, t; }"
        : "=r"(a) : "l"(p));
    return a;
}

#define LDSM4(r0, r1, r2, r3, addr) \
    asm volatile("ldmatrix.sync.aligned.m8n8.x4.shared.b16 {%0,%1,%2,%3}, [%4];" \
                 : "=r"(r0), "=r"(r1), "=r"(r2), "=r"(r3) : "r"(addr))

// ---------------- prep: dtype detect + index decode + degree count ---------
__global__ void k_prep(const void* ebuf, const void* mbuf) {
    const unsigned* eu = (const unsigned*)ebuf;
    const unsigned* mu = (const unsigned*)mbuf;
    int fe = 1, fm = 1;
#pragma unroll
    for (int i = 0; i < 16; i++) if (eu[2 * i + 1] != 0u) { fe = 0; break; }
#pragma unroll
    for (int i = 0; i < 16; i++) if (mu[2 * i + 1] != 0u) { fm = 0; break; }

    int i = blockIdx.x * blockDim.x + threadIdx.x;
    if (i < EP) {
        int s, d;
        if (i < EE) {
            s = load_idx(ebuf, i, fe);
            d = load_idx(ebuf, (long long)EE + i, fe);
        } else {
            s = i - EE;
            d = i - EE;
        }
        g_src[i] = s;
        g_dst[i] = d;
        atomicAdd(&g_cnt[d], 1);
    }
    if (i < MM) g_midx[i] = load_idx(mbuf, i, fm);
}

// ---------------- CSR build ----------------
__global__ void k_scan() {
    __shared__ int wsum[32];
    int tid = threadIdx.x;
    int lane = tid & 31, w = tid >> 5;
    int base = tid * 8;
    int loc[8];
    int s = 0;
#pragma unroll
    for (int i = 0; i < 8; i++) { loc[i] = s; s += g_cnt[base + i]; }
    int inc = s;
#pragma unroll
    for (int o = 1; o < 32; o <<= 1) {
        int v = __shfl_up_sync(~0u, inc, o);
        if (lane >= o) inc += v;
    }
    if (lane == 31) wsum[w] = inc;
    __syncthreads();
    if (w == 0) {
        int v = wsum[lane];
#pragma unroll
        for (int o = 1; o < 32; o <<= 1) {
            int t = __shfl_up_sync(~0u, v, o);
            if (lane >= o) v += t;
        }
        wsum[lane] = v;
    }
    __syncthreads();
    int off = inc - s + (w ? wsum[w - 1] : 0);
#pragma unroll
    for (int i = 0; i < 8; i++) {
        g_rptr[base + i] = off + loc[i];
        g_woff[base + i] = off + loc[i];
    }
    if (tid == 1023) g_rptr[NN] = EP;
}
__global__ void k_fill() {
    int i = blockIdx.x * blockDim.x + threadIdx.x;
    if (i >= EP) return;
    int pos = atomicAdd(&g_woff[g_dst[i]], 1);
    g_csrc[pos] = g_src[i];
}

// ---------------- fused pre-pass: cvt(x) + W1T + W2T + fcwT + clsinit ------
#define NB_CVT 6144
#define NB_W1  (192 * 24)
#define NB_W2  (24 * 192)
#define NB_FC  (24 * 48)
__device__ __forceinline__ void tr_tile(const float* __restrict__ in,
                                        __half* __restrict__ out,
                                        int R, int C, int bx, int by, int tid) {
    __shared__ float t[32][33];
    int tx = tid & 31, ty = tid >> 5;
    int x = bx * 32 + tx;
#pragma unroll
    for (int j = 0; j < 32; j += 8) {
        int y = by * 32 + ty + j;
        t[ty + j][tx] = in[(size_t)y * C + x];
    }
    __syncthreads();
    int ox = by * 32 + tx;
#pragma unroll
    for (int j = 0; j < 32; j += 8) {
        int oy = bx * 32 + ty + j;
        out[(size_t)oy * R + ox] = __float2half(t[tx][ty + j]);
    }
}
__global__ __launch_bounds__(256)
void k_preall(const float4* __restrict__ x4, __half2* __restrict__ xh2,
              const float* __restrict__ W1, __half* __restrict__ W1T,
              const float* __restrict__ W2, __half* __restrict__ W2T,
              const float* __restrict__ fcw, __half* __restrict__ fcwT,
              const float* __restrict__ fcb, const float* __restrict__ clw,
              const float* __restrict__ clb, float* __restrict__ out) {
    int b = blockIdx.x, tid = threadIdx.x;
    if (b < NB_CVT) {
        size_t i = (size_t)b * 256 + tid;
        float4 v = x4[i];
        xh2[2 * i + 0] = __floats2half2_rn(v.x, v.y);
        xh2[2 * i + 1] = __floats2half2_rn(v.z, v.w);
        return;
    }
    b -= NB_CVT;
    if (b < NB_W1) { tr_tile(W1, W1T, DD, F1, b % 192, b / 192, tid); return; }
    b -= NB_W1;
    if (b < NB_W2) { tr_tile(W2, W2T, F1, CC, b % 24, b / 24, tid); return; }
    b -= NB_W2;
    if (b < NB_FC) { tr_tile(fcw, fcwT, 2 * CC, CC, b % 24, b / 24, tid); return; }
    // last block: classifier init  out[m][j] = clb[j] + dot(fcb, clw[:,j])
    {
        __shared__ float r0[8], r1[8];
        int lane = tid & 31, w = tid >> 5;
        float s0 = 0.f, s1 = 0.f;
        for (int c = tid; c < CC; c += 256) {
            float v = fcb[c];
            s0 += v * clw[c * 2 + 0];
            s1 += v * clw[c * 2 + 1];
        }
#pragma unroll
        for (int o = 16; o; o >>= 1) {
            s0 += __shfl_xor_sync(~0u, s0, o);
            s1 += __shfl_xor_sync(~0u, s1, o);
        }
        if (lane == 0) { r0[w] = s0; r1[w] = s1; }
        __syncthreads();
        float c0 = 0.f, c1 = 0.f;
#pragma unroll
        for (int i = 0; i < 8; i++) { c0 += r0[i]; c1 += r1[i]; }
        c0 += clb[0]; c1 += clb[1];
        for (int m = tid; m < MM; m += 256) {
            out[m * 2 + 0] = c0;
            out[m * 2 + 1] = c1;
        }
    }
}

// ---------------- fp16 mma.sync GEMM (3-stage pipeline) --------------------
// MODE 0: plain C store.  MODE 1: C store + fused att dots.  MODE 2: no C
// store; fused classifier (attA = clw, outA = out[M,2], atomicAdd partials).
__device__ __forceinline__ void mma16816(float* c, const uint32_t* a,
                                         const uint32_t* b) {
    asm volatile(
        "mma.sync.aligned.m16n8k16.row.col.f32.f16.f16.f32 "
        "{%0,%1,%2,%3}, {%4,%5,%6,%7}, {%8,%9}, {%0,%1,%2,%3};"
        : "+f"(c[0]), "+f"(c[1]), "+f"(c[2]), "+f"(c[3])
        : "r"(a[0]), "r"(a[1]), "r"(a[2]), "r"(a[3]), "r"(b[0]), "r"(b[1]));
}
template <typename OutT, int MODE>
__global__ __launch_bounds__(GT, 2)
void hgemm(const __half* __restrict__ A, const __half* __restrict__ Bt,
           OutT* __restrict__ C, int Nd, int Kiter, int ldK, size_t partStride,
           const float* __restrict__ attA, const float* __restrict__ attD,
           float* __restrict__ outA, float* __restrict__ outD, int heads) {
    extern __shared__ __half hsm[];
    int tid = threadIdx.x;
    int wid = tid >> 5, lane = tid & 31;
    int wr = wid & 1, wc = wid >> 1;
    int g = lane >> 2, q = lane & 3;
    int row0 = blockIdx.y * BM, col0 = blockIdx.x * BN;
    int koff = blockIdx.z * Kiter;
    C += (size_t)blockIdx.z * partStride;
    const int NIT = Kiter / BK;
    uint32_t sbase = smem_u32(hsm);

    uint32_t a_off = (uint32_t)(((wr * 64 + (lane & 15)) * HPAD
                                 + ((lane & 16) ? 8 : 0)) * 2);
    uint32_t b_off = (uint32_t)(((wc * 32 + (lane & 7) + ((lane & 16) ? 8 : 0)) * HPAD
                                 + ((lane & 8) ? 8 : 0)) * 2);

    auto issue = [&](int s, int kt) {
        uint32_t as = sbase + (uint32_t)(s * 2 * HTILE) * 2u;
        uint32_t bs = as + (uint32_t)HTILE * 2u;
#pragma unroll
        for (int l = 0; l < 2; l++) {
            int p = tid + l * GT;
            int r = p >> 2, c0 = (p & 3) << 3;
            const __half* ga = A + (size_t)(row0 + r) * ldK + koff + kt + c0;
            uint32_t da = as + (uint32_t)(r * HPAD + c0) * 2u;
            asm volatile("cp.async.cg.shared.global [%0], [%1], 16;"
                         :: "r"(da), "l"(ga) : "memory");
            const __half* gb = Bt + (size_t)(col0 + r) * ldK + koff + kt + c0;
            uint32_t db = bs + (uint32_t)(r * HPAD + c0) * 2u;
            asm volatile("cp.async.cg.shared.global [%0], [%1], 16;"
                         :: "r"(db), "l"(gb) : "memory");
        }
        asm volatile("cp.async.commit_group;" ::: "memory");
    };

    float acc[4][4][4];
#pragma unroll
    for (int a = 0; a < 4; a++)
#pragma unroll
        for (int b = 0; b < 4; b++)
#pragma unroll
            for (int c = 0; c < 4; c++) acc[a][b][c] = 0.f;

    issue(0, 0);
    issue(1, BK);

    for (int i = 0; i < NIT; i++) {
        if (i + 2 < NIT) {
            issue((i + 2) % STG, (i + 2) * BK);
            asm volatile("cp.async.wait_group 2;" ::: "memory");
        } else {
            asm volatile("cp.async.wait_group 0;" ::: "memory");
        }
        __syncthreads();

        uint32_t as = sbase + (uint32_t)((i % STG) * 2 * HTILE) * 2u;
        uint32_t bs = as + (uint32_t)HTILE * 2u;
#pragma unroll
        for (int ki = 0; ki < 2; ki++) {
            uint32_t kb2 = (uint32_t)(ki * 16 * 2);
            uint32_t af[4][4], bf[4][2];
#pragma unroll
            for (int mi = 0; mi < 4; mi++) {
                uint32_t addr = as + a_off + (uint32_t)(mi * 16 * HPAD * 2) + kb2;
                LDSM4(af[mi][0], af[mi][1], af[mi][2], af[mi][3], addr);
            }
#pragma unroll
            for (int np = 0; np < 2; np++) {
                uint32_t addr = bs + b_off + (uint32_t)(np * 16 * HPAD * 2) + kb2;
                LDSM4(bf[2 * np][0], bf[2 * np][1],
                      bf[2 * np + 1][0], bf[2 * np + 1][1], addr);
            }
#pragma unroll
            for (int mi = 0; mi < 4; mi++)
#pragma unroll
                for (int ni = 0; ni < 4; ni++)
                    mma16816(acc[mi][ni], af[mi], bf[ni]);
        }
        __syncthreads();
    }

    if (MODE != 2) {
#pragma unroll
        for (int mi = 0; mi < 4; mi++) {
            int r0 = row0 + wr * 64 + mi * 16 + g;
#pragma unroll
            for (int ni = 0; ni < 4; ni++) {
                int col = col0 + wc * 32 + ni * 8 + q * 2;
                OutT* p0 = C + (size_t)r0 * Nd + col;
                OutT* p1 = p0 + (size_t)8 * Nd;
                if (sizeof(OutT) == 2) {
                    *(__half2*)p0 = __floats2half2_rn(acc[mi][ni][0], acc[mi][ni][1]);
                    *(__half2*)p1 = __floats2half2_rn(acc[mi][ni][2], acc[mi][ni][3]);
                } else {
                    p0[0] = (OutT)acc[mi][ni][0]; p0[1] = (OutT)acc[mi][ni][1];
                    p1[0] = (OutT)acc[mi][ni][2]; p1[1] = (OutT)acc[mi][ni][3];
                }
            }
        }
    }

    if (MODE == 1) {
        int head = col0 / CC;
        float a0[4], a1[4], d0[4], d1[4];
#pragma unroll
        for (int ni = 0; ni < 4; ni++) {
            int lc = col0 + wc * 32 + ni * 8 + q * 2;
            a0[ni] = attA[lc]; a1[ni] = attA[lc + 1];
            d0[ni] = attD[lc]; d1[ni] = attD[lc + 1];
        }
#pragma unroll
        for (int mi = 0; mi < 4; mi++) {
            float sa0 = 0.f, sd0 = 0.f, sa1 = 0.f, sd1 = 0.f;
#pragma unroll
            for (int ni = 0; ni < 4; ni++) {
                sa0 += acc[mi][ni][0] * a0[ni] + acc[mi][ni][1] * a1[ni];
                sd0 += acc[mi][ni][0] * d0[ni] + acc[mi][ni][1] * d1[ni];
                sa1 += acc[mi][ni][2] * a0[ni] + acc[mi][ni][3] * a1[ni];
                sd1 += acc[mi][ni][2] * d0[ni] + acc[mi][ni][3] * d1[ni];
            }
#pragma unroll
            for (int o = 1; o < 4; o <<= 1) {
                sa0 += __shfl_xor_sync(~0u, sa0, o);
                sd0 += __shfl_xor_sync(~0u, sd0, o);
                sa1 += __shfl_xor_sync(~0u, sa1, o);
                sd1 += __shfl_xor_sync(~0u, sd1, o);
            }
            if (q == 0) {
                int r0 = row0 + wr * 64 + mi * 16 + g;
                atomicAdd(&outA[r0 * heads + head], sa0);
                atomicAdd(&outD[r0 * heads + head], sd0);
                atomicAdd(&outA[(r0 + 8) * heads + head], sa1);
                atomicAdd(&outD[(r0 + 8) * heads + head], sd1);
            }
        }
    }

    if (MODE == 2) {
        float w0[4], w1[4], v0[4], v1[4];
#pragma unroll
        for (int ni = 0; ni < 4; ni++) {
            int c = col0 + wc * 32 + ni * 8 + q * 2;
            w0[ni] = attA[c * 2 + 0];
            v0[ni] = attA[c * 2 + 1];
            w1[ni] = attA[(c + 1) * 2 + 0];
            v1[ni] = attA[(c + 1) * 2 + 1];
        }
#pragma unroll
        for (int mi = 0; mi < 4; mi++) {
            float sa0 = 0.f, sb0 = 0.f, sa1 = 0.f, sb1 = 0.f;
#pragma unroll
            for (int ni = 0; ni < 4; ni++) {
                sa0 += acc[mi][ni][0] * w0[ni] + acc[mi][ni][1] * w1[ni];
                sb0 += acc[mi][ni][0] * v0[ni] + acc[mi][ni][1] * v1[ni];
                sa1 += acc[mi][ni][2] * w0[ni] + acc[mi][ni][3] * w1[ni];
                sb1 += acc[mi][ni][2] * v0[ni] + acc[mi][ni][3] * v1[ni];
            }
#pragma unroll
            for (int o = 1; o < 4; o <<= 1) {
                sa0 += __shfl_xor_sync(~0u, sa0, o);
                sb0 += __shfl_xor_sync(~0u, sb0, o);
                sa1 += __shfl_xor_sync(~0u, sa1, o);
                sb1 += __shfl_xor_sync(~0u, sb1, o);
            }
            if (q == 0) {
                int r0 = row0 + wr * 64 + mi * 16 + g;
                atomicAdd(&outA[r0 * 2 + 0], sa0);
                atomicAdd(&outA[r0 * 2 + 1], sb0);
                atomicAdd(&outA[(r0 + 8) * 2 + 0], sa1);
                atomicAdd(&outA[(r0 + 8) * 2 + 1], sb1);
            }
        }
    }
}

// ---------------- split-K reduce + layer-2 attention dots ------------------
__global__ __launch_bounds__(256)
void k_red2att(const float* __restrict__ p0, const float* __restrict__ p1,
               const float* __restrict__ as2, const float* __restrict__ ad2,
               float* __restrict__ H2, float* __restrict__ asum,
               float* __restrict__ dsum) {
    int n = blockIdx.x, tid = threadIdx.x;
    int lane = tid & 31, w = tid >> 5;
    const float* a = p0 + (size_t)n * CC;
    const float* b = p1 + (size_t)n * CC;
    float s1 = 0.f, s2 = 0.f;
#pragma unroll
    for (int k = 0; k < 3; k++) {
        int c = tid + k * 256;
        float v = a[c] + b[c];
        H2[(size_t)n * CC + c] = v;
        s1 += v * as2[c];
        s2 += v * ad2[c];
    }
#pragma unroll
    for (int o = 16; o; o >>= 1) {
        s1 += __shfl_xor_sync(~0u, s1, o);
        s2 += __shfl_xor_sync(~0u, s2, o);
    }
    __shared__ float r1[8], r2[8];
    if (lane == 0) { r1[w] = s1; r2[w] = s2; }
    __syncthreads();
    if (tid == 0) {
        float t1 = 0.f, t2 = 0.f;
#pragma unroll
        for (int i = 0; i < 8; i++) { t1 += r1[i]; t2 += r2[i]; }
        asum[n] = t1;
        dsum[n] = t2;
    }
}

// ---------------- fused layer-1 aggregation (fp16, uint4 loads) ------------
#define CH1 64
__global__ __launch_bounds__(256)
void k_agg1(const uint4* __restrict__ H4, const float* __restrict__ asrc,
            const float* __restrict__ adst, const float* __restrict__ bias,
            uint4* __restrict__ out) {
    int d = blockIdx.x;
    int tid = threadIdx.x, wid = tid >> 5, lane = tid & 31;
    int beg = g_rptr[d], end = g_rptr[d + 1];
    __shared__ float s_m[H1H], s_den[H1H];
    __shared__ float s_coef[CH1 * H1H];
    __shared__ int s_src[CH1];

    {
        int h = wid;
        float adh = adst[d * H1H + h];
        float mx = -1e30f;
        for (int i = beg + lane; i < end; i += 32) {
            float v = asrc[g_csrc[i] * H1H + h] + adh;
            v = (v > 0.f) ? v : NEG_SLOPE * v;
            mx = fmaxf(mx, v);
        }
#pragma unroll
        for (int o = 16; o; o >>= 1) mx = fmaxf(mx, __shfl_xor_sync(~0u, mx, o));
        float sum = 0.f;
        for (int i = beg + lane; i < end; i += 32) {
            float v = asrc[g_csrc[i] * H1H + h] + adh;
            v = (v > 0.f) ? v : NEG_SLOPE * v;
            sum += expf(v - mx);
        }
#pragma unroll
        for (int o = 16; o; o >>= 1) sum += __shfl_xor_sync(~0u, sum, o);
        if (lane == 0) { s_m[h] = mx; s_den[h] = sum + 1e-16f; }
    }
    __syncthreads();

    int hk[3][4];
#pragma unroll
    for (int k = 0; k < 3; k++)
#pragma unroll
        for (int j = 0; j < 4; j++)
            hk[k][j] = (4 * (tid + k * 256) + j) / 384;
    float2 acc[3][4];
#pragma unroll
    for (int k = 0; k < 3; k++)
#pragma unroll
        for (int j = 0; j < 4; j++) acc[k][j] = make_float2(0.f, 0.f);

    for (int cb = beg; cb < end; cb += CH1) {
        int ch = min(CH1, end - cb);
        for (int i = tid; i < ch * H1H; i += 256) {
            int e = i >> 3, h = i & 7;
            int s = g_csrc[cb + e];
            float v = asrc[s * H1H + h] + adst[d * H1H + h];
            v = (v > 0.f) ? v : NEG_SLOPE * v;
            s_coef[i] = expf(v - s_m[h]) / s_den[h];
            if (h == 0) s_src[e] = s;
        }
        __syncthreads();
        for (int e = 0; e < ch; e++) {
            const uint4* hp = H4 + (size_t)s_src[e] * (F1 / 8);
            const float* cf = &s_coef[e * H1H];
#pragma unroll
            for (int k = 0; k < 3; k++) {
                uint4 u = hp[tid + k * 256];
                const __half2* hv = (const __half2*)&u;
#pragma unroll
                for (int j = 0; j < 4; j++) {
                    float2 v = __half22float2(hv[j]);
                    float c = cf[hk[k][j]];
                    acc[k][j].x += c * v.x;
                    acc[k][j].y += c * v.y;
                }
            }
        }
        __syncthreads();
    }
#pragma unroll
    for (int k = 0; k < 3; k++) {
        uint4 o;
        __half2* ov = (__half2*)&o;
#pragma unroll
        for (int j = 0; j < 4; j++) {
            int c = 2 * (4 * (tid + k * 256) + j);
            float v0 = acc[k][j].x + bias[c];
            float v1 = acc[k][j].y + bias[c + 1];
            v0 = (v0 > 0.f) ? v0 : expm1f(v0);
            v1 = (v1 > 0.f) ? v1 : expm1f(v1);
            ov[j] = __floats2half2_rn(v0, v1);
        }
        out[(size_t)d * (F1 / 8) + tid + k * 256] = o;
    }
}

// ---------------- fused layer-2 aggregation -> cath (per masked row) -------
// block m: d = midx[m]; aggregates H2 neighbors, writes half(acc + b2) into
// cath[m][0:CC] and half(x[d]) into cath[m][CC:2CC].
#define CH2 128
__global__ __launch_bounds__(256)
void k_agg2cat(const float* __restrict__ H, const float* __restrict__ asrc,
               const float* __restrict__ adst, const float* __restrict__ b2,
               const float* __restrict__ x, __half* __restrict__ cat) {
    int m = blockIdx.x;
    int d = g_midx[m];
    int tid = threadIdx.x, wid = tid >> 5, lane = tid & 31;
    int beg = g_rptr[d], end = g_rptr[d + 1];
    __shared__ float s_m, s_den;
    __shared__ float s_coef[CH2];
    __shared__ int s_src[CH2];

    if (wid == 0) {
        float adh = adst[d];
        float mx = -1e30f;
        for (int i = beg + lane; i < end; i += 32) {
            float v = asrc[g_csrc[i]] + adh;
            v = (v > 0.f) ? v : NEG_SLOPE * v;
            mx = fmaxf(mx, v);
        }
#pragma unroll
        for (int o = 16; o; o >>= 1) mx = fmaxf(mx, __shfl_xor_sync(~0u, mx, o));
        float sum = 0.f;
        for (int i = beg + lane; i < end; i += 32) {
            float v = asrc[g_csrc[i]] + adh;
            v = (v > 0.f) ? v : NEG_SLOPE * v;
            sum += expf(v - mx);
        }
#pragma unroll
        for (int o = 16; o; o >>= 1) sum += __shfl_xor_sync(~0u, sum, o);
        if (lane == 0) { s_m = mx; s_den = sum + 1e-16f; }
    }
    __syncthreads();

    float acc[3] = {0.f, 0.f, 0.f};
    for (int cb = beg; cb < end; cb += CH2) {
        int ch = min(CH2, end - cb);
        for (int i = tid; i < ch; i += 256) {
            int s = g_csrc[cb + i];
            float v = asrc[s] + adst[d];
            v = (v > 0.f) ? v : NEG_SLOPE * v;
            s_coef[i] = expf(v - s_m) / s_den;
            s_src[i] = s;
        }
        __syncthreads();
        for (int e = 0; e < ch; e++) {
            const float* hp = H + (size_t)s_src[e] * CC;
            float cf = s_coef[e];
#pragma unroll
            for (int k = 0; k < 3; k++)
                acc[k] += cf * hp[tid + k * 256];
        }
        __syncthreads();
    }
    __half* cm = cat + (size_t)m * (2 * CC);
#pragma unroll
    for (int k = 0; k < 3; k++) {
        int c = tid + k * 256;
        cm[c] = __float2half(acc[k] + b2[c]);
        cm[CC + c] = __float2half(x[(size_t)d * DD + c]);
    }
}

// ---------------- launch ----------------
extern "C" void kernel_launch(void* const* d_in, const int* in_sizes, int n_in,
                              void* d_out, int out_size) {
    (void)in_sizes; (void)n_in; (void)out_size;
    const float* x   = (const float*)d_in[0];
    const void*  eix = d_in[1];
    const void*  mix = d_in[2];
    const float* W1  = (const float*)d_in[3];
    const float* as1 = (const float*)d_in[4];
    const float* ad1 = (const float*)d_in[5];
    const float* b1  = (const float*)d_in[6];
    const float* W2  = (const float*)d_in[7];
    const float* as2 = (const float*)d_in[8];
    const float* ad2 = (const float*)d_in[9];
    const float* b2  = (const float*)d_in[10];
    const float* fcw = (const float*)d_in[11];
    const float* fcb = (const float*)d_in[12];
    const float* clw = (const float*)d_in[13];
    const float* clb = (const float*)d_in[14];
    float* out = (float*)d_out;

    void *pH1h, *pOut1h, *pH2p, *pXh, *pAtt1, *pAs2, *pAd2;
    void *pCath, *pW1T, *pW2T, *pFcwTh, *pCnt;
    cudaGetSymbolAddress(&pH1h, g_H1h);
    cudaGetSymbolAddress(&pOut1h, g_out1h);
    cudaGetSymbolAddress(&pH2p, g_H2p);
    cudaGetSymbolAddress(&pXh, g_xh);
    cudaGetSymbolAddress(&pAtt1, g_att1);
    cudaGetSymbolAddress(&pAs2, g_asrc2);
    cudaGetSymbolAddress(&pAd2, g_adst2);
    cudaGetSymbolAddress(&pCath, g_cath);
    cudaGetSymbolAddress(&pW1T, g_W1T);
    cudaGetSymbolAddress(&pW2T, g_W2T);
    cudaGetSymbolAddress(&pFcwTh, g_fcwTh);
    cudaGetSymbolAddress(&pCnt, g_cnt);

    float* As1 = (float*)pAtt1;
    float* Ad1 = (float*)pAtt1 + (size_t)NN * H1H;
    float* H2  = (float*)pH2p;
    float* H2b = (float*)pH2p + (size_t)NN * CC;

    const int H_SMEM = STG * 2 * HTILE * 2;   // 61440 B
    cudaFuncSetAttribute(hgemm<__half, 1>,
                         cudaFuncAttributeMaxDynamicSharedMemorySize, H_SMEM);
    cudaFuncSetAttribute(hgemm<float, 0>,
                         cudaFuncAttributeMaxDynamicSharedMemorySize, H_SMEM);
    cudaFuncSetAttribute(hgemm<float, 2>,
                         cudaFuncAttributeMaxDynamicSharedMemorySize, H_SMEM);

    cudaMemsetAsync(pCnt, 0, NN * sizeof(int));
    cudaMemsetAsync(pAtt1, 0, (size_t)2 * NN * H1H * sizeof(float));
    k_prep<<<(EP + 255) / 256, 256>>>(eix, mix);
    k_scan<<<1, 1024>>>();
    k_fill<<<(EP + 255) / 256, 256>>>();

    k_preall<<<NB_CVT + NB_W1 + NB_W2 + NB_FC + 1, 256>>>(
        (const float4*)x, (__half2*)pXh,
        W1, (__half*)pW1T, W2, (__half*)pW2T, fcw, (__half*)pFcwTh,
        fcb, clw, clb, out);

    // ---- layer 1 (att dots fused into epilogue) ----
    hgemm<__half, 1><<<dim3(F1 / BN, NN / BM, 1), GT, H_SMEM>>>(
        (const __half*)pXh, (const __half*)pW1T, (__half*)pH1h,
        F1, DD, DD, 0, as1, ad1, As1, Ad1, H1H);
    k_agg1<<<NN, 256>>>((const uint4*)pH1h, As1, Ad1, b1, (uint4*)pOut1h);

    // ---- layer 2 (split-K=2; reduce fuses att dots) ----
    hgemm<float, 0><<<dim3(CC / BN, NN / BM, 2), GT, H_SMEM>>>(
        (const __half*)pOut1h, (const __half*)pW2T, H2,
        CC, F1 / 2, F1, (size_t)NN * CC, nullptr, nullptr, nullptr, nullptr, 1);
    k_red2att<<<NN, 256>>>(H2, H2b, as2, ad2, H2, (float*)pAs2, (float*)pAd2);

    // ---- fused agg2 + concat (masked rows only) ----
    k_agg2cat<<<MM, 256>>>(H2, (const float*)pAs2, (const float*)pAd2, b2, x,
                           (__half*)pCath);

    // ---- head: fc GEMM with fused classifier ----
    hgemm<float, 2><<<dim3(CC / BN, MM / BM, 1), GT, H_SMEM>>>(
        (const __half*)pCath, (const __half*)pFcwTh, (float*)nullptr,
        CC, 2 * CC, 2 * CC, 0, clw, nullptr, out, nullptr, 1);
}